// round 7
// baseline (speedup 1.0000x reference)
#include <cuda_runtime.h>
#include <cuda_bf16.h>
#include <cuda_fp16.h>
#include <math.h>
#include <stdint.h>

// ---------------- problem constants ----------------
#define B_    256
#define L_    197
#define LP    196
#define D_    768
#define HD    512
#define DH    128
#define NH    4
#define NC    1000
#define FLATN 2883   // 3*31*31
#define LPAD  208    // 196 padded to multiple of 16

// ---------------- scratch (static __device__, no allocation) ----------------
__device__ float g_xp[(size_t)B_ * LP * HD];          // 50176 x 512
__device__ float g_mean[NH * B_];                     // (pad kernel target)
__device__ float g_cov[(size_t)B_ * 3 * DH * DH];     // (b,p,d,e) NCHW
__device__ float g_flat[(size_t)B_ * FLATN];

// fp16 buffers for tensor-core projection GEMM
__device__ __half gA_h[(size_t)B_ * LP * D_];    // [50176,768]
__device__ __half gWt_h[(size_t)HD * D_];        // [512,768]  W^T hi
__device__ __half gWt_l[(size_t)HD * D_];        // [512,768]  W^T lo

// centered+transposed LN output, fp16 hi/lo: (h,b, d=128, l=208)
__device__ __half gHn_h[(size_t)NH * B_ * DH * LPAD];
__device__ __half gHn_l[(size_t)NH * B_ * DH * LPAD];

// ---------------- baseline-PTX helpers ----------------
__device__ __forceinline__ uint32_t smem_u32(const void* p) {
    uint32_t a;
    asm("{ .reg .u64 t; cvta.to.shared.u64 t, %1; cvt.u32.u64 %0, t; }"
        : "=r"(a) : "l"(p));
    return a;
}
__device__ __forceinline__ void cp16(uint32_t dst, const void* src) {
    asm volatile("cp.async.ca.shared.global [%0], [%1], 16;"
                 :: "r"(dst), "l"(src) : "memory");
}
#define CP_COMMIT() asm volatile("cp.async.commit_group;" ::: "memory")
#define CP_WAIT0()  asm volatile("cp.async.wait_group 0;" ::: "memory")
#define CP_WAIT1()  asm volatile("cp.async.wait_group 1;" ::: "memory")
#define CP_WAIT2()  asm volatile("cp.async.wait_group 2;" ::: "memory")

__device__ __forceinline__ void ldx4(uint32_t* r, uint32_t addr) {
    asm volatile("ldmatrix.sync.aligned.m8n8.x4.shared.b16 {%0,%1,%2,%3}, [%4];"
                 : "=r"(r[0]), "=r"(r[1]), "=r"(r[2]), "=r"(r[3]) : "r"(addr));
}
__device__ __forceinline__ void mma16816(float* c, const uint32_t* a,
                                         uint32_t b0, uint32_t b1) {
    asm volatile(
        "mma.sync.aligned.m16n8k16.row.col.f32.f16.f16.f32 "
        "{%0,%1,%2,%3}, {%4,%5,%6,%7}, {%8,%9}, {%0,%1,%2,%3};"
        : "+f"(c[0]), "+f"(c[1]), "+f"(c[2]), "+f"(c[3])
        : "r"(a[0]), "r"(a[1]), "r"(a[2]), "r"(a[3]), "r"(b0), "r"(b1));
}

// =====================================================================
// K0a: round x[:,1:,:] to fp16  [50176,768]
// =====================================================================
__global__ void __launch_bounds__(256) k_convA(const float* __restrict__ X)
{
    const int total = B_ * LP * (D_ / 4);
    for (int i = blockIdx.x * blockDim.x + threadIdx.x; i < total;
         i += gridDim.x * blockDim.x) {
        const int m  = i / (D_ / 4);
        const int k4 = i - m * (D_ / 4);
        const int b  = m / LP;
        const int l  = m - b * LP + 1;
        float4 v = *(const float4*)(X + ((size_t)(b * L_ + l)) * D_ + k4 * 4);
        __half2 h01, h23;
        h01.x = __float2half_rn(v.x); h01.y = __float2half_rn(v.y);
        h23.x = __float2half_rn(v.z); h23.y = __float2half_rn(v.w);
        ((__half2*)gA_h)[(size_t)i * 2]     = h01;
        ((__half2*)gA_h)[(size_t)i * 2 + 1] = h23;
    }
}

// =====================================================================
// K0b: W [768,512] -> W^T split fp16 hi/lo [512,768]
// =====================================================================
__global__ void __launch_bounds__(256) k_convW(const float* __restrict__ W)
{
    __shared__ float t[32][33];
    const int nb = blockIdx.x * 32;
    const int kb = blockIdx.y * 32;
    const int tx = threadIdx.x, ty = threadIdx.y;
#pragma unroll
    for (int r = 0; r < 32; r += 8)
        t[ty + r][tx] = W[(size_t)(kb + ty + r) * HD + nb + tx];
    __syncthreads();
#pragma unroll
    for (int r = 0; r < 32; r += 8) {
        const float v = t[tx][ty + r];
        const __half h  = __float2half_rn(v);
        const __half lo = __float2half_rn(v - __half2float(h));
        const size_t o = (size_t)(nb + ty + r) * D_ + kb + tx;
        gWt_h[o] = h;
        gWt_l[o] = lo;
    }
}

// =====================================================================
// K0c: pad kernel (keeps GEMM at ncu's captured launch index 3)
// =====================================================================
__global__ void __launch_bounds__(256) k_zmean()
{
    for (int i = threadIdx.x + blockIdx.x * 256; i < NH * B_; i += 256 * 4)
        g_mean[i] = 0.f;
}

// =====================================================================
// K1: warp-mma fp16 2-pass GEMM: xp = A_h @ (B_h + B_l)
// CTA tile 128x128, BK=32, 8 warps (4x2), 3-stage cp.async pipeline.
// =====================================================================
#define RSB      80
#define TILE_B   (128 * RSB)
#define OFF_AH   0
#define OFF_BH   (1 * TILE_B)
#define OFF_BL   (2 * TILE_B)
#define STAGE_B  (3 * TILE_B)          // 30720
#define GEMM_SMEM (3 * STAGE_B)        // 92160 (3 stages)
#define NCHUNK   (D_ / 32)             // 24

__device__ __forceinline__ void gemm_load_stage(
    uint32_t sb, int buf, int c, int m0, int n0, int tid)
{
    const int k0 = c * 32;
    const uint32_t stg = sb + buf * STAGE_B;
#pragma unroll
    for (int q = 0; q < 2; q++) {
        const int ch  = q * 256 + tid;
        const int row = ch >> 2;
        const int cc  = ch & 3;
        const uint32_t doff = (uint32_t)row * RSB + cc * 16;
        const size_t ga = (size_t)(m0 + row) * D_ + k0 + cc * 8;
        const size_t gb = (size_t)(n0 + row) * D_ + k0 + cc * 8;
        cp16(stg + OFF_AH + doff, gA_h + ga);
        cp16(stg + OFF_BH + doff, gWt_h + gb);
        cp16(stg + OFF_BL + doff, gWt_l + gb);
    }
}

__global__ void __launch_bounds__(256) k_gemm_mma(const float* __restrict__ bias)
{
    extern __shared__ char smem[];
    const uint32_t sb = smem_u32(smem);
    const int tid  = threadIdx.x;
    const int wid  = tid >> 5;
    const int lane = tid & 31;
    const int wm = wid >> 1;
    const int wn = wid & 1;
    const int m0 = blockIdx.x * 128;
    const int n0 = blockIdx.y * 128;

    const uint32_t a_row = (lane & 15);
    const uint32_t a_col = (uint32_t)(lane >> 4) * 16;
    const uint32_t b_row = (lane & 7) + ((lane >> 4) << 3);
    const uint32_t b_col = (uint32_t)((lane >> 3) & 1) * 16;

    uint32_t a_off[2], b_off[4];
#pragma unroll
    for (int mt = 0; mt < 2; mt++)
        a_off[mt] = (uint32_t)(wm * 32 + mt * 16 + a_row) * RSB + a_col;
#pragma unroll
    for (int g = 0; g < 4; g++)
        b_off[g] = (uint32_t)(wn * 64 + g * 16 + b_row) * RSB + b_col;

    float acc[2][8][4];
#pragma unroll
    for (int mt = 0; mt < 2; mt++)
#pragma unroll
        for (int nt = 0; nt < 8; nt++)
#pragma unroll
            for (int e = 0; e < 4; e++) acc[mt][nt][e] = 0.f;

    gemm_load_stage(sb, 0, 0, m0, n0, tid);
    CP_COMMIT();
    gemm_load_stage(sb, 1, 1, m0, n0, tid);
    CP_COMMIT();

    for (int c = 0; c < NCHUNK; c++) {
        if (c + 2 < NCHUNK) {
            gemm_load_stage(sb, (c + 2) % 3, c + 2, m0, n0, tid);
            CP_COMMIT();
            CP_WAIT2();
        } else if (c + 1 < NCHUNK) {
            CP_WAIT1();
        } else {
            CP_WAIT0();
        }
        __syncthreads();

        const uint32_t stg = sb + (c % 3) * STAGE_B;
#pragma unroll
        for (int ks = 0; ks < 2; ks++) {
            const uint32_t kb = (uint32_t)ks * 32;
            uint32_t ah[2][4];
#pragma unroll
            for (int mt = 0; mt < 2; mt++)
                ldx4(ah[mt], stg + OFF_AH + a_off[mt] + kb);
#pragma unroll
            for (int g = 0; g < 4; g++) {
                uint32_t bh[4], bl[4];
                ldx4(bh, stg + OFF_BH + b_off[g] + kb);
                ldx4(bl, stg + OFF_BL + b_off[g] + kb);
                // hi pass (chain distance 4), then lo pass
                mma16816(acc[0][2 * g],     ah[0], bh[0], bh[1]);
                mma16816(acc[1][2 * g],     ah[1], bh[0], bh[1]);
                mma16816(acc[0][2 * g + 1], ah[0], bh[2], bh[3]);
                mma16816(acc[1][2 * g + 1], ah[1], bh[2], bh[3]);
                mma16816(acc[0][2 * g],     ah[0], bl[0], bl[1]);
                mma16816(acc[1][2 * g],     ah[1], bl[0], bl[1]);
                mma16816(acc[0][2 * g + 1], ah[0], bl[2], bl[3]);
                mma16816(acc[1][2 * g + 1], ah[1], bl[2], bl[3]);
            }
        }
        __syncthreads();
    }

    const int gid = lane >> 2;
    const int tig = lane & 3;
#pragma unroll
    for (int mt = 0; mt < 2; mt++) {
        const int r0 = m0 + wm * 32 + mt * 16 + gid;
#pragma unroll
        for (int nt = 0; nt < 8; nt++) {
            const int col = n0 + wn * 64 + nt * 8 + 2 * tig;
            const float b0 = bias[col], b1 = bias[col + 1];
            float2 v0 = make_float2(acc[mt][nt][0] + b0, acc[mt][nt][1] + b1);
            float2 v1 = make_float2(acc[mt][nt][2] + b0, acc[mt][nt][3] + b1);
            *(float2*)(g_xp + (size_t)r0 * HD + col)       = v0;
            *(float2*)(g_xp + (size_t)(r0 + 8) * HD + col) = v1;
        }
    }
}

// =====================================================================
// K2: fused LayerNorm + (h,b)-mean centering + transpose + fp16 split
// One block per (h,b). smem tile rows padded to 132 floats (528 B,
// 16B-aligned for float4 stores -- 129 was the R6 misalignment bug).
// Output: gHn_h/gHn_l as (h,b, d, l) with l padded to 208 (zeros).
// =====================================================================
#define LNR 132
#define LNC_SMEM (LP * LNR * 4)   // 103,488 B

__global__ void __launch_bounds__(256) k_lnc(
    const float* __restrict__ g, const float* __restrict__ be)
{
    extern __shared__ float ls[];
    __shared__ float wsum[8];
    __shared__ float s_mu;

    const int h = blockIdx.x >> 8;
    const int b = blockIdx.x & 255;
    const int tid  = threadIdx.x;
    const int warp = tid >> 5;
    const int lane = tid & 31;

    const float4 gv = *(const float4*)(g + lane * 4);
    const float4 bv = *(const float4*)(be + lane * 4);

    float tsum = 0.f;
    for (int l = warp; l < LP; l += 8) {
        const float* src = g_xp + ((size_t)(b * LP + l)) * HD + h * DH;
        float4 v = *(const float4*)(src + lane * 4);

        float s = v.x + v.y + v.z + v.w;
#pragma unroll
        for (int o = 16; o; o >>= 1) s += __shfl_xor_sync(0xffffffffu, s, o);
        const float mu = s * (1.0f / 128.0f);

        const float d0 = v.x - mu, d1 = v.y - mu, d2 = v.z - mu, d3 = v.w - mu;
        float sq = d0 * d0 + d1 * d1 + d2 * d2 + d3 * d3;
#pragma unroll
        for (int o = 16; o; o >>= 1) sq += __shfl_xor_sync(0xffffffffu, sq, o);
        const float rstd = rsqrtf(sq * (1.0f / 128.0f) + 1e-5f);

        float4 o4;
        o4.x = d0 * rstd * gv.x + bv.x;
        o4.y = d1 * rstd * gv.y + bv.y;
        o4.z = d2 * rstd * gv.z + bv.z;
        o4.w = d3 * rstd * gv.w + bv.w;
        *(float4*)(ls + l * LNR + lane * 4) = o4;
        tsum += o4.x + o4.y + o4.z + o4.w;
    }
#pragma unroll
    for (int o = 16; o; o >>= 1) tsum += __shfl_xor_sync(0xffffffffu, tsum, o);
    if (lane == 0) wsum[warp] = tsum;
    __syncthreads();
    if (tid == 0) {
        float t = 0.f;
#pragma unroll
        for (int w = 0; w < 8; w++) t += wsum[w];
        s_mu = t * (1.0f / (LP * DH));
    }
    __syncthreads();
    const float mu = s_mu;

    // transposed fp16 hi/lo write: (d, l) rows, l padded 196->208 with zeros
    __half* dst_h = gHn_h + ((size_t)(h * B_ + b)) * DH * LPAD;
    __half* dst_l = gHn_l + ((size_t)(h * B_ + b)) * DH * LPAD;
    for (int idx = tid; idx < DH * (LPAD / 2); idx += 256) {
        const int d  = idx / (LPAD / 2);
        const int j  = idx % (LPAD / 2);
        const int l0 = 2 * j;
        float a0 = (l0 < LP)     ? ls[l0 * LNR + d] - mu       : 0.f;
        float a1 = (l0 + 1 < LP) ? ls[(l0 + 1) * LNR + d] - mu : 0.f;
        const __half h0 = __float2half_rn(a0);
        const __half h1 = __float2half_rn(a1);
        __half2 hh; hh.x = h0; hh.y = h1;
        __half2 ll;
        ll.x = __float2half_rn(a0 - __half2float(h0));
        ll.y = __float2half_rn(a1 - __half2float(h1));
        *(__half2*)(dst_h + (size_t)d * LPAD + l0) = hh;
        *(__half2*)(dst_l + (size_t)d * LPAD + l0) = ll;
    }
}

// =====================================================================
// K3: cov via fp16 mma (2-pass asymmetric): C = A_h · (B_h + B_l)^T
// contraction over l (K=208). Block per (p,b). Epilogue: column-L2
// normalize: out = acc / max(sqrt(colsq), Lp*eps)  (== ref /Lp, /nrm)
// =====================================================================
#define CRS  216                       // padded row stride (halves)
#define CRSB (CRS * 2)                 // 432 bytes = 27 * 16B
#define CTILE_B (DH * CRSB)            // 55296
#define COV_SMEM (3 * CTILE_B)         // 165,888

__global__ void __launch_bounds__(256) k_cov_mma()
{
    extern __shared__ char csm[];
    const uint32_t sb = smem_u32(csm);
    __shared__ float colsq[DH];

    const int p = blockIdx.x;   // 0..2
    const int b = blockIdx.y;   // 0..255
    const int tid  = threadIdx.x;
    const int wid  = tid >> 5;
    const int lane = tid & 31;
    const int wm = wid >> 1;
    const int wn = wid & 1;

    const __half* Asrc = gHn_h + ((size_t)(p * B_ + b)) * DH * LPAD;
    const __half* Bhs  = gHn_h + ((size_t)((p + 1) * B_ + b)) * DH * LPAD;
    const __half* Bls  = gHn_l + ((size_t)((p + 1) * B_ + b)) * DH * LPAD;

    const uint32_t tA = sb, tBh = sb + CTILE_B, tBl = sb + 2 * CTILE_B;
    for (int t = tid; t < DH * 26; t += 256) {
        const int row = t / 26;
        const int ch  = t % 26;
        const uint32_t doff = (uint32_t)row * CRSB + ch * 16;
        const size_t   goff = (size_t)row * LPAD + ch * 8;
        cp16(tA  + doff, Asrc + goff);
        cp16(tBh + doff, Bhs + goff);
        cp16(tBl + doff, Bls + goff);
    }
    CP_COMMIT();
    if (tid < DH) colsq[tid] = 0.f;
    CP_WAIT0();
    __syncthreads();

    const uint32_t a_row = (lane & 15);
    const uint32_t a_col = (uint32_t)(lane >> 4) * 16;
    const uint32_t b_row = (lane & 7) + ((lane >> 4) << 3);
    const uint32_t b_col = (uint32_t)((lane >> 3) & 1) * 16;

    uint32_t a_off[2], b_off[4];
#pragma unroll
    for (int mt = 0; mt < 2; mt++)
        a_off[mt] = (uint32_t)(wm * 32 + mt * 16 + a_row) * CRSB + a_col;
#pragma unroll
    for (int g = 0; g < 4; g++)
        b_off[g] = (uint32_t)(wn * 64 + g * 16 + b_row) * CRSB + b_col;

    float acc[2][8][4];
#pragma unroll
    for (int mt = 0; mt < 2; mt++)
#pragma unroll
        for (int nt = 0; nt < 8; nt++)
#pragma unroll
            for (int e = 0; e < 4; e++) acc[mt][nt][e] = 0.f;

#pragma unroll
    for (int ks = 0; ks < LPAD / 16; ks++) {     // 13 steps
        const uint32_t kb = (uint32_t)ks * 32;
        uint32_t ah[2][4];
#pragma unroll
        for (int mt = 0; mt < 2; mt++)
            ldx4(ah[mt], tA + a_off[mt] + kb);
#pragma unroll
        for (int g = 0; g < 4; g++) {
            uint32_t bh[4], bl[4];
            ldx4(bh, tBh + b_off[g] + kb);
            ldx4(bl, tBl + b_off[g] + kb);
            mma16816(acc[0][2 * g],     ah[0], bh[0], bh[1]);
            mma16816(acc[1][2 * g],     ah[1], bh[0], bh[1]);
            mma16816(acc[0][2 * g + 1], ah[0], bh[2], bh[3]);
            mma16816(acc[1][2 * g + 1], ah[1], bh[2], bh[3]);
            mma16816(acc[0][2 * g],     ah[0], bl[0], bl[1]);
            mma16816(acc[1][2 * g],     ah[1], bl[0], bl[1]);
            mma16816(acc[0][2 * g + 1], ah[0], bl[2], bl[3]);
            mma16816(acc[1][2 * g + 1], ah[1], bl[2], bl[3]);
        }
    }

    // column sum-of-squares (over all 128 rows) per column e
#pragma unroll
    for (int nt = 0; nt < 8; nt++) {
        float s0 = acc[0][nt][0] * acc[0][nt][0] + acc[0][nt][2] * acc[0][nt][2]
                 + acc[1][nt][0] * acc[1][nt][0] + acc[1][nt][2] * acc[1][nt][2];
        float s1 = acc[0][nt][1] * acc[0][nt][1] + acc[0][nt][3] * acc[0][nt][3]
                 + acc[1][nt][1] * acc[1][nt][1] + acc[1][nt][3] * acc[1][nt][3];
#pragma unroll
        for (int o = 4; o <= 16; o <<= 1) {
            s0 += __shfl_xor_sync(0xffffffffu, s0, o);
            s1 += __shfl_xor_sync(0xffffffffu, s1, o);
        }
        if (lane < 4) {
            const int col = wn * 64 + nt * 8 + 2 * lane;
            atomicAdd(&colsq[col], s0);
            atomicAdd(&colsq[col + 1], s1);
        }
    }
    __syncthreads();

    const int gid = lane >> 2;
    const int tig = lane & 3;
    float* outb = g_cov + ((size_t)(b * 3 + p)) * (DH * DH);
#pragma unroll
    for (int nt = 0; nt < 8; nt++) {
        const int col = wn * 64 + nt * 8 + 2 * tig;
        const float i0 = 1.0f / fmaxf(sqrtf(colsq[col]),     (float)LP * 1e-12f);
        const float i1 = 1.0f / fmaxf(sqrtf(colsq[col + 1]), (float)LP * 1e-12f);
#pragma unroll
        for (int mt = 0; mt < 2; mt++) {
            const int r0 = wm * 32 + mt * 16 + gid;
            float2 v0 = make_float2(acc[mt][nt][0] * i0, acc[mt][nt][1] * i1);
            float2 v1 = make_float2(acc[mt][nt][2] * i0, acc[mt][nt][3] * i1);
            *(float2*)(outb + (size_t)r0 * DH + col)       = v0;
            *(float2*)(outb + (size_t)(r0 + 8) * DH + col) = v1;
        }
    }
}

// =====================================================================
// K4: fused conv1 -> GELU -> conv2, cov staged in smem (2 y-phases)
// =====================================================================
#define CONV_CS_B  (3 * 66 * 128 * 4)          // 101,376
#define CONV_SMEM  (CONV_CS_B + 3 * 3969 * 4)  // + 47,628 = 149,004

__global__ void __launch_bounds__(256) k_conv(
    const float* __restrict__ w1, const float* __restrict__ w2)
{
    extern __shared__ char cvsm[];
    float* cs = (float*)cvsm;                  // [3][66][128]
    float* z1 = (float*)(cvsm + CONV_CS_B);    // [3][63][63]
    __shared__ float w1s[81];
    __shared__ float w2s[81];

    const int b = blockIdx.x;
    const int tid = threadIdx.x;
    if (tid < 81) { w1s[tid] = w1[tid]; w2s[tid] = w2[tid]; }

    const float* cb = g_cov + (size_t)b * 3 * DH * DH;

#pragma unroll 1
    for (int ph = 0; ph < 2; ph++) {
        const int r0 = ph * 64;
        const int nr = ph ? 64 : 66;
        const int y0 = ph ? 32 : 0;
        const int ny = ph ? 31 : 32;
        __syncthreads();
        for (int i = tid; i < 3 * nr * 32; i += 256) {
            const int c  = i / (nr * 32);
            const int rr = (i / 32) % nr;
            const int q  = i % 32;
            *(float4*)(cs + (c * 66 + rr) * 128 + q * 4) =
                *(const float4*)(cb + (size_t)c * (DH * DH) + (r0 + rr) * DH + q * 4);
        }
        __syncthreads();
        for (int idx = tid; idx < 3 * ny * 63; idx += 256) {
            const int c = idx / (ny * 63);
            const int r = idx % (ny * 63);
            const int y = y0 + r / 63;
            const int x = r % 63;
            float s = 0.f;
#pragma unroll
            for (int ci = 0; ci < 3; ci++)
#pragma unroll
                for (int ky = 0; ky < 3; ky++)
#pragma unroll
                    for (int kx = 0; kx < 3; kx++)
                        s += cs[(ci * 66 + (2 * y + ky - r0)) * 128 + 2 * x + kx]
                           * w1s[((c * 3 + ci) * 3 + ky) * 3 + kx];
            s = 0.5f * s * (1.0f + erff(s * 0.70710678118654752f));
            z1[c * 3969 + y * 63 + x] = s;
        }
    }
    __syncthreads();

    for (int idx = tid; idx < FLATN; idx += 256) {
        const int c = idx / 961;
        const int r = idx % 961;
        const int y = r / 31, x = r % 31;
        float s = 0.f;
#pragma unroll
        for (int ci = 0; ci < 3; ci++)
#pragma unroll
            for (int ky = 0; ky < 3; ky++)
#pragma unroll
                for (int kx = 0; kx < 3; kx++)
                    s += z1[ci * 3969 + (2 * y + ky) * 63 + (2 * x + kx)]
                       * w2s[((c * 3 + ci) * 3 + ky) * 3 + kx];
        g_flat[(size_t)b * FLATN + idx] = s;
    }
}

// =====================================================================
// K5: classifier head
// =====================================================================
__global__ void __launch_bounds__(256) k_head(
    const float* __restrict__ cls, const float* __restrict__ w1,
    const float* __restrict__ b1, const float* __restrict__ w2,
    const float* __restrict__ b2, float* __restrict__ out)
{
    const int n  = blockIdx.x * 256 + threadIdx.x;
    const int b0 = blockIdx.y * 8;
    const bool ok = (n < NC);

    float acc[8];
#pragma unroll
    for (int i = 0; i < 8; i++) acc[i] = 0.f;

    __shared__ float As[8][64];

    for (int k0 = 0; k0 < D_; k0 += 64) {
        for (int q = threadIdx.x; q < 512; q += 256) {
            const int bi = q >> 6, kk = q & 63;
            As[bi][kk] = cls[(size_t)(b0 + bi) * D_ + k0 + kk];
        }
        __syncthreads();
        if (ok) {
#pragma unroll 8
            for (int kk = 0; kk < 64; kk++) {
                const float w = w1[(size_t)(k0 + kk) * NC + n];
#pragma unroll
                for (int bi = 0; bi < 8; bi++) acc[bi] += As[bi][kk] * w;
            }
        }
        __syncthreads();
    }

    for (int c = 0; c < 45; c++) {
        const int k0 = c * 64;
        for (int q = threadIdx.x; q < 512; q += 256) {
            const int bi = q >> 6, kk = q & 63;
            As[bi][kk] = g_flat[(size_t)(b0 + bi) * FLATN + k0 + kk];
        }
        __syncthreads();
        if (ok) {
#pragma unroll 8
            for (int kk = 0; kk < 64; kk++) {
                const float w = w2[(size_t)(k0 + kk) * NC + n];
#pragma unroll
                for (int bi = 0; bi < 8; bi++) acc[bi] += As[bi][kk] * w;
            }
        }
        __syncthreads();
    }
    {
        const int k0 = 2880;
        if (threadIdx.x < 8 * 3) {
            const int bi = threadIdx.x / 3, kk = threadIdx.x % 3;
            As[bi][kk] = g_flat[(size_t)(b0 + bi) * FLATN + k0 + kk];
        }
        __syncthreads();
        if (ok) {
            for (int kk = 0; kk < 3; kk++) {
                const float w = w2[(size_t)(k0 + kk) * NC + n];
#pragma unroll
                for (int bi = 0; bi < 8; bi++) acc[bi] += As[bi][kk] * w;
            }
        }
    }

    if (ok) {
        const float bb = b1[n] + b2[n];
#pragma unroll
        for (int bi = 0; bi < 8; bi++)
            out[(size_t)(b0 + bi) * NC + n] = (acc[bi] + bb) * 0.5f;
    }
}

// =====================================================================
// launch
// =====================================================================
extern "C" void kernel_launch(void* const* d_in, const int* in_sizes, int n_in,
                              void* d_out, int out_size)
{
    const float* cls_token = (const float*)d_in[0];
    const float* x         = (const float*)d_in[1];
    const float* proj_w    = (const float*)d_in[2];
    const float* proj_b    = (const float*)d_in[3];
    const float* ln_g      = (const float*)d_in[4];
    const float* ln_b      = (const float*)d_in[5];
    const float* conv1_w   = (const float*)d_in[6];
    const float* conv2_w   = (const float*)d_in[7];
    const float* cls1_w    = (const float*)d_in[8];
    const float* cls1_b    = (const float*)d_in[9];
    const float* cls2_w    = (const float*)d_in[10];
    const float* cls2_b    = (const float*)d_in[11];
    float* out = (float*)d_out;

    cudaFuncSetAttribute(k_gemm_mma,
                         cudaFuncAttributeMaxDynamicSharedMemorySize, GEMM_SMEM);
    cudaFuncSetAttribute(k_lnc,
                         cudaFuncAttributeMaxDynamicSharedMemorySize, LNC_SMEM);
    cudaFuncSetAttribute(k_cov_mma,
                         cudaFuncAttributeMaxDynamicSharedMemorySize, COV_SMEM);
    cudaFuncSetAttribute(k_conv,
                         cudaFuncAttributeMaxDynamicSharedMemorySize, CONV_SMEM);

    k_convA<<<2048, 256>>>(x);                                    // 0
    k_convW<<<dim3(HD / 32, D_ / 32), dim3(32, 8)>>>(proj_w);     // 1
    k_zmean<<<4, 256>>>();                                        // 2 (pad)
    k_gemm_mma<<<dim3(392, 4), 256, GEMM_SMEM>>>(proj_b);         // 3 <- ncu
    k_lnc<<<NH * B_, 256, LNC_SMEM>>>(ln_g, ln_b);                // 4
    k_cov_mma<<<dim3(3, B_), 256, COV_SMEM>>>();                  // 5
    k_conv<<<B_, 256, CONV_SMEM>>>(conv1_w, conv2_w);             // 6
    k_head<<<dim3(4, 32), 256>>>(cls_token, cls1_w, cls1_b, cls2_w, cls2_b, out);
}

// round 8
// speedup vs baseline: 1.0456x; 1.0456x over previous
#include <cuda_runtime.h>
#include <cuda_bf16.h>
#include <cuda_fp16.h>
#include <math.h>
#include <stdint.h>

// ---------------- problem constants ----------------
#define B_    256
#define L_    197
#define LP    196
#define D_    768
#define HD    512
#define DH    128
#define NH    4
#define NC    1000
#define FLATN 2883   // 3*31*31
#define LPAD  208    // 196 padded to multiple of 16

// ---------------- scratch (static __device__, no allocation) ----------------
__device__ float g_xp[(size_t)B_ * LP * HD];          // 50176 x 512
__device__ float g_cov[(size_t)B_ * 3 * DH * DH];     // (b,p,d,e) NCHW
__device__ float g_flat[(size_t)B_ * FLATN];

// fp16 buffers for tensor-core projection GEMM
__device__ __half gA_h[(size_t)B_ * LP * D_];    // [50176,768]
__device__ __half gWt_h[(size_t)HD * D_];        // [512,768]  W^T hi
__device__ __half gWt_l[(size_t)HD * D_];        // [512,768]  W^T lo

// centered+transposed LN output, fp16 hi/lo: (h,b, d=128, l=208)
__device__ __half gHn_h[(size_t)NH * B_ * DH * LPAD];
__device__ __half gHn_l[(size_t)NH * B_ * DH * LPAD];

// ---------------- baseline-PTX helpers ----------------
__device__ __forceinline__ uint32_t smem_u32(const void* p) {
    uint32_t a;
    asm("{ .reg .u64 t; cvta.to.shared.u64 t, %1; cvt.u32.u64 %0, t; }"
        : "=r"(a) : "l"(p));
    return a;
}
__device__ __forceinline__ void cp16(uint32_t dst, const void* src) {
    asm volatile("cp.async.ca.shared.global [%0], [%1], 16;"
                 :: "r"(dst), "l"(src) : "memory");
}
#define CP_COMMIT() asm volatile("cp.async.commit_group;" ::: "memory")
#define CP_WAIT0()  asm volatile("cp.async.wait_group 0;" ::: "memory")
#define CP_WAIT1()  asm volatile("cp.async.wait_group 1;" ::: "memory")

__device__ __forceinline__ void ldx4(uint32_t* r, uint32_t addr) {
    asm volatile("ldmatrix.sync.aligned.m8n8.x4.shared.b16 {%0,%1,%2,%3}, [%4];"
                 : "=r"(r[0]), "=r"(r[1]), "=r"(r[2]), "=r"(r[3]) : "r"(addr));
}
__device__ __forceinline__ void mma16816(float* c, const uint32_t* a,
                                         uint32_t b0, uint32_t b1) {
    asm volatile(
        "mma.sync.aligned.m16n8k16.row.col.f32.f16.f16.f32 "
        "{%0,%1,%2,%3}, {%4,%5,%6,%7}, {%8,%9}, {%0,%1,%2,%3};"
        : "+f"(c[0]), "+f"(c[1]), "+f"(c[2]), "+f"(c[3])
        : "r"(a[0]), "r"(a[1]), "r"(a[2]), "r"(a[3]), "r"(b0), "r"(b1));
}

// =====================================================================
// K0a: round x[:,1:,:] to fp16  [50176,768]
// =====================================================================
__global__ void __launch_bounds__(256) k_convA(const float* __restrict__ X)
{
    const int total = B_ * LP * (D_ / 4);
    for (int i = blockIdx.x * blockDim.x + threadIdx.x; i < total;
         i += gridDim.x * blockDim.x) {
        const int m  = i / (D_ / 4);
        const int k4 = i - m * (D_ / 4);
        const int b  = m / LP;
        const int l  = m - b * LP + 1;
        float4 v = *(const float4*)(X + ((size_t)(b * L_ + l)) * D_ + k4 * 4);
        __half2 h01, h23;
        h01.x = __float2half_rn(v.x); h01.y = __float2half_rn(v.y);
        h23.x = __float2half_rn(v.z); h23.y = __float2half_rn(v.w);
        ((__half2*)gA_h)[(size_t)i * 2]     = h01;
        ((__half2*)gA_h)[(size_t)i * 2 + 1] = h23;
    }
}

// =====================================================================
// K0b: W [768,512] -> W^T split fp16 hi/lo [512,768]
// =====================================================================
__global__ void __launch_bounds__(256) k_convW(const float* __restrict__ W)
{
    __shared__ float t[32][33];
    const int nb = blockIdx.x * 32;
    const int kb = blockIdx.y * 32;
    const int tx = threadIdx.x, ty = threadIdx.y;
#pragma unroll
    for (int r = 0; r < 32; r += 8)
        t[ty + r][tx] = W[(size_t)(kb + ty + r) * HD + nb + tx];
    __syncthreads();
#pragma unroll
    for (int r = 0; r < 32; r += 8) {
        const float v = t[tx][ty + r];
        const __half h  = __float2half_rn(v);
        const __half lo = __float2half_rn(v - __half2float(h));
        const size_t o = (size_t)(nb + ty + r) * D_ + kb + tx;
        gWt_h[o] = h;
        gWt_l[o] = lo;
    }
}

// =====================================================================
// K1: warp-mma fp16 2-pass GEMM: xp = A_h @ (B_h + B_l)
// CTA tile 128x128, BK=32, 8 warps (4x2), TWO-stage cp.async pipeline
// (R5 schedule -- measured 216us / tensor 60.4%; R7's 3-stage regressed)
// =====================================================================
#define RSB      80
#define TILE_B   (128 * RSB)
#define OFF_AH   0
#define OFF_BH   (1 * TILE_B)
#define OFF_BL   (2 * TILE_B)
#define STAGE_B  (3 * TILE_B)          // 30720
#define GEMM_SMEM (2 * STAGE_B)        // 61440
#define NCHUNK   (D_ / 32)             // 24

__device__ __forceinline__ void gemm_load_stage(
    uint32_t sb, int buf, int c, int m0, int n0, int tid)
{
    const int k0 = c * 32;
    const uint32_t stg = sb + buf * STAGE_B;
#pragma unroll
    for (int q = 0; q < 2; q++) {
        const int ch  = q * 256 + tid;
        const int row = ch >> 2;
        const int cc  = ch & 3;
        const uint32_t doff = (uint32_t)row * RSB + cc * 16;
        const size_t ga = (size_t)(m0 + row) * D_ + k0 + cc * 8;
        const size_t gb = (size_t)(n0 + row) * D_ + k0 + cc * 8;
        cp16(stg + OFF_AH + doff, gA_h + ga);
        cp16(stg + OFF_BH + doff, gWt_h + gb);
        cp16(stg + OFF_BL + doff, gWt_l + gb);
    }
}

__global__ void __launch_bounds__(256) k_gemm_mma(const float* __restrict__ bias)
{
    extern __shared__ char smem[];
    const uint32_t sb = smem_u32(smem);
    const int tid  = threadIdx.x;
    const int wid  = tid >> 5;
    const int lane = tid & 31;
    const int wm = wid >> 1;
    const int wn = wid & 1;
    const int m0 = blockIdx.x * 128;
    const int n0 = blockIdx.y * 128;

    const uint32_t a_row = (lane & 15);
    const uint32_t a_col = (uint32_t)(lane >> 4) * 16;
    const uint32_t b_row = (lane & 7) + ((lane >> 4) << 3);
    const uint32_t b_col = (uint32_t)((lane >> 3) & 1) * 16;

    uint32_t a_off[2], b_off[4];
#pragma unroll
    for (int mt = 0; mt < 2; mt++)
        a_off[mt] = (uint32_t)(wm * 32 + mt * 16 + a_row) * RSB + a_col;
#pragma unroll
    for (int g = 0; g < 4; g++)
        b_off[g] = (uint32_t)(wn * 64 + g * 16 + b_row) * RSB + b_col;

    float acc[2][8][4];
#pragma unroll
    for (int mt = 0; mt < 2; mt++)
#pragma unroll
        for (int nt = 0; nt < 8; nt++)
#pragma unroll
            for (int e = 0; e < 4; e++) acc[mt][nt][e] = 0.f;

    gemm_load_stage(sb, 0, 0, m0, n0, tid);
    CP_COMMIT();

    for (int c = 0; c < NCHUNK; c++) {
        if (c + 1 < NCHUNK) {
            gemm_load_stage(sb, (c + 1) & 1, c + 1, m0, n0, tid);
            CP_COMMIT();
            CP_WAIT1();
        } else {
            CP_WAIT0();
        }
        __syncthreads();

        const uint32_t stg = sb + (c & 1) * STAGE_B;
#pragma unroll
        for (int ks = 0; ks < 2; ks++) {
            const uint32_t kb = (uint32_t)ks * 32;
            uint32_t ah[2][4];
#pragma unroll
            for (int mt = 0; mt < 2; mt++)
                ldx4(ah[mt], stg + OFF_AH + a_off[mt] + kb);
#pragma unroll
            for (int g = 0; g < 4; g++) {
                uint32_t bh[4], bl[4];
                ldx4(bh, stg + OFF_BH + b_off[g] + kb);
                ldx4(bl, stg + OFF_BL + b_off[g] + kb);
#pragma unroll
                for (int mt = 0; mt < 2; mt++) {
                    mma16816(acc[mt][2 * g],     ah[mt], bh[0], bh[1]);
                    mma16816(acc[mt][2 * g],     ah[mt], bl[0], bl[1]);
                    mma16816(acc[mt][2 * g + 1], ah[mt], bh[2], bh[3]);
                    mma16816(acc[mt][2 * g + 1], ah[mt], bl[2], bl[3]);
                }
            }
        }
        __syncthreads();
    }

    const int gid = lane >> 2;
    const int tig = lane & 3;
#pragma unroll
    for (int mt = 0; mt < 2; mt++) {
        const int r0 = m0 + wm * 32 + mt * 16 + gid;
#pragma unroll
        for (int nt = 0; nt < 8; nt++) {
            const int col = n0 + wn * 64 + nt * 8 + 2 * tig;
            const float b0 = bias[col], b1 = bias[col + 1];
            float2 v0 = make_float2(acc[mt][nt][0] + b0, acc[mt][nt][1] + b1);
            float2 v1 = make_float2(acc[mt][nt][2] + b0, acc[mt][nt][3] + b1);
            *(float2*)(g_xp + (size_t)r0 * HD + col)       = v0;
            *(float2*)(g_xp + (size_t)(r0 + 8) * HD + col) = v1;
        }
    }
}

// =====================================================================
// K2: fused LayerNorm + (h,b)-mean centering + transpose + fp16 split
// One block per (h,b). smem rows padded to 132 floats (16B-aligned).
// Output: gHn_h/gHn_l as (h,b, d, l) with l padded to 208 (zeros).
// (launch index 3 this round -> ncu probe target)
// =====================================================================
#define LNR 132
#define LNC_SMEM (LP * LNR * 4)   // 103,488 B

__global__ void __launch_bounds__(256) k_lnc(
    const float* __restrict__ g, const float* __restrict__ be)
{
    extern __shared__ float ls[];
    __shared__ float wsum[8];
    __shared__ float s_mu;

    const int h = blockIdx.x >> 8;
    const int b = blockIdx.x & 255;
    const int tid  = threadIdx.x;
    const int warp = tid >> 5;
    const int lane = tid & 31;

    const float4 gv = *(const float4*)(g + lane * 4);
    const float4 bv = *(const float4*)(be + lane * 4);

    float tsum = 0.f;
    for (int l = warp; l < LP; l += 8) {
        const float* src = g_xp + ((size_t)(b * LP + l)) * HD + h * DH;
        float4 v = *(const float4*)(src + lane * 4);

        float s = v.x + v.y + v.z + v.w;
#pragma unroll
        for (int o = 16; o; o >>= 1) s += __shfl_xor_sync(0xffffffffu, s, o);
        const float mu = s * (1.0f / 128.0f);

        const float d0 = v.x - mu, d1 = v.y - mu, d2 = v.z - mu, d3 = v.w - mu;
        float sq = d0 * d0 + d1 * d1 + d2 * d2 + d3 * d3;
#pragma unroll
        for (int o = 16; o; o >>= 1) sq += __shfl_xor_sync(0xffffffffu, sq, o);
        const float rstd = rsqrtf(sq * (1.0f / 128.0f) + 1e-5f);

        float4 o4;
        o4.x = d0 * rstd * gv.x + bv.x;
        o4.y = d1 * rstd * gv.y + bv.y;
        o4.z = d2 * rstd * gv.z + bv.z;
        o4.w = d3 * rstd * gv.w + bv.w;
        *(float4*)(ls + l * LNR + lane * 4) = o4;
        tsum += o4.x + o4.y + o4.z + o4.w;
    }
#pragma unroll
    for (int o = 16; o; o >>= 1) tsum += __shfl_xor_sync(0xffffffffu, tsum, o);
    if (lane == 0) wsum[warp] = tsum;
    __syncthreads();
    if (tid == 0) {
        float t = 0.f;
#pragma unroll
        for (int w = 0; w < 8; w++) t += wsum[w];
        s_mu = t * (1.0f / (LP * DH));
    }
    __syncthreads();
    const float mu = s_mu;

    __half* dst_h = gHn_h + ((size_t)(h * B_ + b)) * DH * LPAD;
    __half* dst_l = gHn_l + ((size_t)(h * B_ + b)) * DH * LPAD;
    for (int idx = tid; idx < DH * (LPAD / 2); idx += 256) {
        const int d  = idx / (LPAD / 2);
        const int j  = idx % (LPAD / 2);
        const int l0 = 2 * j;
        float a0 = (l0 < LP)     ? ls[l0 * LNR + d] - mu       : 0.f;
        float a1 = (l0 + 1 < LP) ? ls[(l0 + 1) * LNR + d] - mu : 0.f;
        const __half h0 = __float2half_rn(a0);
        const __half h1 = __float2half_rn(a1);
        __half2 hh; hh.x = h0; hh.y = h1;
        __half2 ll;
        ll.x = __float2half_rn(a0 - __half2float(h0));
        ll.y = __float2half_rn(a1 - __half2float(h1));
        *(__half2*)(dst_h + (size_t)d * LPAD + l0) = hh;
        *(__half2*)(dst_l + (size_t)d * LPAD + l0) = ll;
    }
}

// =====================================================================
// K3: cov via fp16 mma (2-pass asymmetric): C = A_h · (B_h + B_l)^T
// =====================================================================
#define CRS  216
#define CRSB (CRS * 2)                 // 432 bytes = 27 * 16B
#define CTILE_B (DH * CRSB)            // 55296
#define COV_SMEM (3 * CTILE_B)         // 165,888

__global__ void __launch_bounds__(256) k_cov_mma()
{
    extern __shared__ char csm[];
    const uint32_t sb = smem_u32(csm);
    __shared__ float colsq[DH];

    const int p = blockIdx.x;
    const int b = blockIdx.y;
    const int tid  = threadIdx.x;
    const int wid  = tid >> 5;
    const int lane = tid & 31;
    const int wm = wid >> 1;
    const int wn = wid & 1;

    const __half* Asrc = gHn_h + ((size_t)(p * B_ + b)) * DH * LPAD;
    const __half* Bhs  = gHn_h + ((size_t)((p + 1) * B_ + b)) * DH * LPAD;
    const __half* Bls  = gHn_l + ((size_t)((p + 1) * B_ + b)) * DH * LPAD;

    const uint32_t tA = sb, tBh = sb + CTILE_B, tBl = sb + 2 * CTILE_B;
    for (int t = tid; t < DH * 26; t += 256) {
        const int row = t / 26;
        const int ch  = t % 26;
        const uint32_t doff = (uint32_t)row * CRSB + ch * 16;
        const size_t   goff = (size_t)row * LPAD + ch * 8;
        cp16(tA  + doff, Asrc + goff);
        cp16(tBh + doff, Bhs + goff);
        cp16(tBl + doff, Bls + goff);
    }
    CP_COMMIT();
    if (tid < DH) colsq[tid] = 0.f;
    CP_WAIT0();
    __syncthreads();

    const uint32_t a_row = (lane & 15);
    const uint32_t a_col = (uint32_t)(lane >> 4) * 16;
    const uint32_t b_row = (lane & 7) + ((lane >> 4) << 3);
    const uint32_t b_col = (uint32_t)((lane >> 3) & 1) * 16;

    uint32_t a_off[2], b_off[4];
#pragma unroll
    for (int mt = 0; mt < 2; mt++)
        a_off[mt] = (uint32_t)(wm * 32 + mt * 16 + a_row) * CRSB + a_col;
#pragma unroll
    for (int g = 0; g < 4; g++)
        b_off[g] = (uint32_t)(wn * 64 + g * 16 + b_row) * CRSB + b_col;

    float acc[2][8][4];
#pragma unroll
    for (int mt = 0; mt < 2; mt++)
#pragma unroll
        for (int nt = 0; nt < 8; nt++)
#pragma unroll
            for (int e = 0; e < 4; e++) acc[mt][nt][e] = 0.f;

#pragma unroll
    for (int ks = 0; ks < LPAD / 16; ks++) {
        const uint32_t kb = (uint32_t)ks * 32;
        uint32_t ah[2][4];
#pragma unroll
        for (int mt = 0; mt < 2; mt++)
            ldx4(ah[mt], tA + a_off[mt] + kb);
#pragma unroll
        for (int g = 0; g < 4; g++) {
            uint32_t bh[4], bl[4];
            ldx4(bh, tBh + b_off[g] + kb);
            ldx4(bl, tBl + b_off[g] + kb);
#pragma unroll
            for (int mt = 0; mt < 2; mt++) {
                mma16816(acc[mt][2 * g],     ah[mt], bh[0], bh[1]);
                mma16816(acc[mt][2 * g],     ah[mt], bl[0], bl[1]);
                mma16816(acc[mt][2 * g + 1], ah[mt], bh[2], bh[3]);
                mma16816(acc[mt][2 * g + 1], ah[mt], bl[2], bl[3]);
            }
        }
    }

#pragma unroll
    for (int nt = 0; nt < 8; nt++) {
        float s0 = acc[0][nt][0] * acc[0][nt][0] + acc[0][nt][2] * acc[0][nt][2]
                 + acc[1][nt][0] * acc[1][nt][0] + acc[1][nt][2] * acc[1][nt][2];
        float s1 = acc[0][nt][1] * acc[0][nt][1] + acc[0][nt][3] * acc[0][nt][3]
                 + acc[1][nt][1] * acc[1][nt][1] + acc[1][nt][3] * acc[1][nt][3];
#pragma unroll
        for (int o = 4; o <= 16; o <<= 1) {
            s0 += __shfl_xor_sync(0xffffffffu, s0, o);
            s1 += __shfl_xor_sync(0xffffffffu, s1, o);
        }
        if (lane < 4) {
            const int col = wn * 64 + nt * 8 + 2 * lane;
            atomicAdd(&colsq[col], s0);
            atomicAdd(&colsq[col + 1], s1);
        }
    }
    __syncthreads();

    const int gid = lane >> 2;
    const int tig = lane & 3;
    float* outb = g_cov + ((size_t)(b * 3 + p)) * (DH * DH);
#pragma unroll
    for (int nt = 0; nt < 8; nt++) {
        const int col = wn * 64 + nt * 8 + 2 * tig;
        const float i0 = 1.0f / fmaxf(sqrtf(colsq[col]),     (float)LP * 1e-12f);
        const float i1 = 1.0f / fmaxf(sqrtf(colsq[col + 1]), (float)LP * 1e-12f);
#pragma unroll
        for (int mt = 0; mt < 2; mt++) {
            const int r0 = wm * 32 + mt * 16 + gid;
            float2 v0 = make_float2(acc[mt][nt][0] * i0, acc[mt][nt][1] * i1);
            float2 v1 = make_float2(acc[mt][nt][2] * i0, acc[mt][nt][3] * i1);
            *(float2*)(outb + (size_t)r0 * DH + col)       = v0;
            *(float2*)(outb + (size_t)(r0 + 8) * DH + col) = v1;
        }
    }
}

// =====================================================================
// K4: fused conv1 -> GELU -> conv2, cov staged in smem (2 y-phases)
// =====================================================================
#define CONV_CS_B  (3 * 66 * 128 * 4)
#define CONV_SMEM  (CONV_CS_B + 3 * 3969 * 4)  // 149,004

__global__ void __launch_bounds__(256) k_conv(
    const float* __restrict__ w1, const float* __restrict__ w2)
{
    extern __shared__ char cvsm[];
    float* cs = (float*)cvsm;
    float* z1 = (float*)(cvsm + CONV_CS_B);
    __shared__ float w1s[81];
    __shared__ float w2s[81];

    const int b = blockIdx.x;
    const int tid = threadIdx.x;
    if (tid < 81) { w1s[tid] = w1[tid]; w2s[tid] = w2[tid]; }

    const float* cb = g_cov + (size_t)b * 3 * DH * DH;

#pragma unroll 1
    for (int ph = 0; ph < 2; ph++) {
        const int r0 = ph * 64;
        const int nr = ph ? 64 : 66;
        const int y0 = ph ? 32 : 0;
        const int ny = ph ? 31 : 32;
        __syncthreads();
        for (int i = tid; i < 3 * nr * 32; i += 256) {
            const int c  = i / (nr * 32);
            const int rr = (i / 32) % nr;
            const int q  = i % 32;
            *(float4*)(cs + (c * 66 + rr) * 128 + q * 4) =
                *(const float4*)(cb + (size_t)c * (DH * DH) + (r0 + rr) * DH + q * 4);
        }
        __syncthreads();
        for (int idx = tid; idx < 3 * ny * 63; idx += 256) {
            const int c = idx / (ny * 63);
            const int r = idx % (ny * 63);
            const int y = y0 + r / 63;
            const int x = r % 63;
            float s = 0.f;
#pragma unroll
            for (int ci = 0; ci < 3; ci++)
#pragma unroll
                for (int ky = 0; ky < 3; ky++)
#pragma unroll
                    for (int kx = 0; kx < 3; kx++)
                        s += cs[(ci * 66 + (2 * y + ky - r0)) * 128 + 2 * x + kx]
                           * w1s[((c * 3 + ci) * 3 + ky) * 3 + kx];
            s = 0.5f * s * (1.0f + erff(s * 0.70710678118654752f));
            z1[c * 3969 + y * 63 + x] = s;
        }
    }
    __syncthreads();

    for (int idx = tid; idx < FLATN; idx += 256) {
        const int c = idx / 961;
        const int r = idx % 961;
        const int y = r / 31, x = r % 31;
        float s = 0.f;
#pragma unroll
        for (int ci = 0; ci < 3; ci++)
#pragma unroll
            for (int ky = 0; ky < 3; ky++)
#pragma unroll
                for (int kx = 0; kx < 3; kx++)
                    s += z1[ci * 3969 + (2 * y + ky) * 63 + (2 * x + kx)]
                       * w2s[((c * 3 + ci) * 3 + ky) * 3 + kx];
        g_flat[(size_t)b * FLATN + idx] = s;
    }
}

// =====================================================================
// K5: classifier head
// =====================================================================
__global__ void __launch_bounds__(256) k_head(
    const float* __restrict__ cls, const float* __restrict__ w1,
    const float* __restrict__ b1, const float* __restrict__ w2,
    const float* __restrict__ b2, float* __restrict__ out)
{
    const int n  = blockIdx.x * 256 + threadIdx.x;
    const int b0 = blockIdx.y * 8;
    const bool ok = (n < NC);

    float acc[8];
#pragma unroll
    for (int i = 0; i < 8; i++) acc[i] = 0.f;

    __shared__ float As[8][64];

    for (int k0 = 0; k0 < D_; k0 += 64) {
        for (int q = threadIdx.x; q < 512; q += 256) {
            const int bi = q >> 6, kk = q & 63;
            As[bi][kk] = cls[(size_t)(b0 + bi) * D_ + k0 + kk];
        }
        __syncthreads();
        if (ok) {
#pragma unroll 8
            for (int kk = 0; kk < 64; kk++) {
                const float w = w1[(size_t)(k0 + kk) * NC + n];
#pragma unroll
                for (int bi = 0; bi < 8; bi++) acc[bi] += As[bi][kk] * w;
            }
        }
        __syncthreads();
    }

    for (int c = 0; c < 45; c++) {
        const int k0 = c * 64;
        for (int q = threadIdx.x; q < 512; q += 256) {
            const int bi = q >> 6, kk = q & 63;
            As[bi][kk] = g_flat[(size_t)(b0 + bi) * FLATN + k0 + kk];
        }
        __syncthreads();
        if (ok) {
#pragma unroll 8
            for (int kk = 0; kk < 64; kk++) {
                const float w = w2[(size_t)(k0 + kk) * NC + n];
#pragma unroll
                for (int bi = 0; bi < 8; bi++) acc[bi] += As[bi][kk] * w;
            }
        }
        __syncthreads();
    }
    {
        const int k0 = 2880;
        if (threadIdx.x < 8 * 3) {
            const int bi = threadIdx.x / 3, kk = threadIdx.x % 3;
            As[bi][kk] = g_flat[(size_t)(b0 + bi) * FLATN + k0 + kk];
        }
        __syncthreads();
        if (ok) {
            for (int kk = 0; kk < 3; kk++) {
                const float w = w2[(size_t)(k0 + kk) * NC + n];
#pragma unroll
                for (int bi = 0; bi < 8; bi++) acc[bi] += As[bi][kk] * w;
            }
        }
    }

    if (ok) {
        const float bb = b1[n] + b2[n];
#pragma unroll
        for (int bi = 0; bi < 8; bi++)
            out[(size_t)(b0 + bi) * NC + n] = (acc[bi] + bb) * 0.5f;
    }
}

// =====================================================================
// launch
// =====================================================================
extern "C" void kernel_launch(void* const* d_in, const int* in_sizes, int n_in,
                              void* d_out, int out_size)
{
    const float* cls_token = (const float*)d_in[0];
    const float* x         = (const float*)d_in[1];
    const float* proj_w    = (const float*)d_in[2];
    const float* proj_b    = (const float*)d_in[3];
    const float* ln_g      = (const float*)d_in[4];
    const float* ln_b      = (const float*)d_in[5];
    const float* conv1_w   = (const float*)d_in[6];
    const float* conv2_w   = (const float*)d_in[7];
    const float* cls1_w    = (const float*)d_in[8];
    const float* cls1_b    = (const float*)d_in[9];
    const float* cls2_w    = (const float*)d_in[10];
    const float* cls2_b    = (const float*)d_in[11];
    float* out = (float*)d_out;

    cudaFuncSetAttribute(k_gemm_mma,
                         cudaFuncAttributeMaxDynamicSharedMemorySize, GEMM_SMEM);
    cudaFuncSetAttribute(k_lnc,
                         cudaFuncAttributeMaxDynamicSharedMemorySize, LNC_SMEM);
    cudaFuncSetAttribute(k_cov_mma,
                         cudaFuncAttributeMaxDynamicSharedMemorySize, COV_SMEM);
    cudaFuncSetAttribute(k_conv,
                         cudaFuncAttributeMaxDynamicSharedMemorySize, CONV_SMEM);

    k_convA<<<2048, 256>>>(x);                                    // 0
    k_convW<<<dim3(HD / 32, D_ / 32), dim3(32, 8)>>>(proj_w);     // 1
    k_gemm_mma<<<dim3(392, 4), 256, GEMM_SMEM>>>(proj_b);         // 2
    k_lnc<<<NH * B_, 256, LNC_SMEM>>>(ln_g, ln_b);                // 3 <- ncu probe
    k_cov_mma<<<dim3(3, B_), 256, COV_SMEM>>>();                  // 4
    k_conv<<<B_, 256, CONV_SMEM>>>(conv1_w, conv2_w);             // 5
    k_head<<<dim3(4, 32), 256>>>(cls_token, cls1_w, cls1_b, cls2_w, cls2_b, out);
}

// round 9
// speedup vs baseline: 1.0797x; 1.0326x over previous
#include <cuda_runtime.h>
#include <cuda_bf16.h>
#include <cuda_fp16.h>
#include <math.h>
#include <stdint.h>

// ---------------- problem constants ----------------
#define B_    256
#define L_    197
#define LP    196
#define D_    768
#define HD    512
#define DH    128
#define NH    4
#define NC    1000
#define FLATN 2883   // 3*31*31

// ---------------- scratch (static __device__, no allocation) ----------------
__device__ float g_xp[(size_t)B_ * LP * HD];          // 50176 x 512
__device__ float g_cov[(size_t)B_ * 3 * DH * DH];     // (b,p,d,e) NCHW
__device__ float g_flat[(size_t)B_ * FLATN];

// fp16 buffers for tensor-core projection GEMM
__device__ __half gA_h[(size_t)B_ * LP * D_];    // [50176,768]
__device__ __half gWt_h[(size_t)HD * D_];        // [512,768]  W^T hi
__device__ __half gWt_l[(size_t)HD * D_];        // [512,768]  W^T lo

// LN output (UNcentered), fp16 hi/lo, natural layout (h,b, l=196, d=128)
__device__ __half gHn_h[(size_t)NH * B_ * LP * DH];
__device__ __half gHn_l[(size_t)NH * B_ * LP * DH];
// column sums + tile means for rank-1 centering correction
__device__ float gSh[(size_t)NH * B_ * DH];   // sum_l hi(hn)
__device__ float gSf[(size_t)NH * B_ * DH];   // sum_l hn (float)
__device__ float gM [(size_t)NH * B_];        // tile mean

// ---------------- baseline-PTX helpers ----------------
__device__ __forceinline__ uint32_t smem_u32(const void* p) {
    uint32_t a;
    asm("{ .reg .u64 t; cvta.to.shared.u64 t, %1; cvt.u32.u64 %0, t; }"
        : "=r"(a) : "l"(p));
    return a;
}
__device__ __forceinline__ void cp16(uint32_t dst, const void* src) {
    asm volatile("cp.async.ca.shared.global [%0], [%1], 16;"
                 :: "r"(dst), "l"(src) : "memory");
}
#define CP_COMMIT() asm volatile("cp.async.commit_group;" ::: "memory")
#define CP_WAIT0()  asm volatile("cp.async.wait_group 0;" ::: "memory")
#define CP_WAIT1()  asm volatile("cp.async.wait_group 1;" ::: "memory")

__device__ __forceinline__ void ldx4(uint32_t* r, uint32_t addr) {
    asm volatile("ldmatrix.sync.aligned.m8n8.x4.shared.b16 {%0,%1,%2,%3}, [%4];"
                 : "=r"(r[0]), "=r"(r[1]), "=r"(r[2]), "=r"(r[3]) : "r"(addr));
}
__device__ __forceinline__ void ldx4t(uint32_t* r, uint32_t addr) {
    asm volatile("ldmatrix.sync.aligned.m8n8.x4.trans.shared.b16 {%0,%1,%2,%3}, [%4];"
                 : "=r"(r[0]), "=r"(r[1]), "=r"(r[2]), "=r"(r[3]) : "r"(addr));
}
__device__ __forceinline__ void mma16816(float* c, const uint32_t* a,
                                         uint32_t b0, uint32_t b1) {
    asm volatile(
        "mma.sync.aligned.m16n8k16.row.col.f32.f16.f16.f32 "
        "{%0,%1,%2,%3}, {%4,%5,%6,%7}, {%8,%9}, {%0,%1,%2,%3};"
        : "+f"(c[0]), "+f"(c[1]), "+f"(c[2]), "+f"(c[3])
        : "r"(a[0]), "r"(a[1]), "r"(a[2]), "r"(a[3]), "r"(b0), "r"(b1));
}

// =====================================================================
// K0: fused prep -- blocks [0,2048): round x to fp16; [2048,2432): W^T split
// =====================================================================
__global__ void __launch_bounds__(256) k_prep(
    const float* __restrict__ X, const float* __restrict__ W)
{
    __shared__ float t[32][33];
    const int tid = threadIdx.x;
    if (blockIdx.x < 2048) {
        const int total = B_ * LP * (D_ / 4);
        for (int i = blockIdx.x * 256 + tid; i < total; i += 2048 * 256) {
            const int m  = i / (D_ / 4);
            const int k4 = i - m * (D_ / 4);
            const int b  = m / LP;
            const int l  = m - b * LP + 1;
            float4 v = *(const float4*)(X + ((size_t)(b * L_ + l)) * D_ + k4 * 4);
            __half2 h01, h23;
            h01.x = __float2half_rn(v.x); h01.y = __float2half_rn(v.y);
            h23.x = __float2half_rn(v.z); h23.y = __float2half_rn(v.w);
            ((__half2*)gA_h)[(size_t)i * 2]     = h01;
            ((__half2*)gA_h)[(size_t)i * 2 + 1] = h23;
        }
    } else {
        const int wb = blockIdx.x - 2048;          // 0..383
        const int nb = (wb & 15) * 32;             // HD dim
        const int kb = (wb >> 4) * 32;             // D dim
        const int tx = tid & 31, ty = tid >> 5;    // (32,8)
#pragma unroll
        for (int r = 0; r < 32; r += 8)
            t[ty + r][tx] = W[(size_t)(kb + ty + r) * HD + nb + tx];
        __syncthreads();
#pragma unroll
        for (int r = 0; r < 32; r += 8) {
            const float v = t[tx][ty + r];
            const __half h  = __float2half_rn(v);
            const __half lo = __float2half_rn(v - __half2float(h));
            const size_t o = (size_t)(nb + ty + r) * D_ + kb + tx;
            gWt_h[o] = h;
            gWt_l[o] = lo;
        }
    }
}

// =====================================================================
// K1: warp-mma fp16 2-pass GEMM: xp = A_h @ (B_h + B_l)
// CTA tile 128x128, BK=32, 8 warps. NEW warp tile 64x32 (wm 0..1, wn 0..3)
// -> 8 ldx4 per 32 mma per warp per k16 (was 10:16, LDS-bound).
// Two-stage cp.async pipeline (R5-proven schedule).
// =====================================================================
#define RSB      80
#define TILE_B   (128 * RSB)
#define OFF_AH   0
#define OFF_BH   (1 * TILE_B)
#define OFF_BL   (2 * TILE_B)
#define STAGE_B  (3 * TILE_B)          // 30720
#define GEMM_SMEM (2 * STAGE_B)        // 61440
#define NCHUNK   (D_ / 32)             // 24

__device__ __forceinline__ void gemm_load_stage(
    uint32_t sb, int buf, int c, int m0, int n0, int tid)
{
    const int k0 = c * 32;
    const uint32_t stg = sb + buf * STAGE_B;
#pragma unroll
    for (int q = 0; q < 2; q++) {
        const int ch  = q * 256 + tid;
        const int row = ch >> 2;
        const int cc  = ch & 3;
        const uint32_t doff = (uint32_t)row * RSB + cc * 16;
        const size_t ga = (size_t)(m0 + row) * D_ + k0 + cc * 8;
        const size_t gb = (size_t)(n0 + row) * D_ + k0 + cc * 8;
        cp16(stg + OFF_AH + doff, gA_h + ga);
        cp16(stg + OFF_BH + doff, gWt_h + gb);
        cp16(stg + OFF_BL + doff, gWt_l + gb);
    }
}

__global__ void __launch_bounds__(256) k_gemm_mma(const float* __restrict__ bias)
{
    extern __shared__ char smem[];
    const uint32_t sb = smem_u32(smem);
    const int tid  = threadIdx.x;
    const int wid  = tid >> 5;
    const int lane = tid & 31;
    const int wm = wid >> 2;              // 0..1 (m 64 each)
    const int wn = wid & 3;               // 0..3 (n 32 each)
    const int m0 = blockIdx.x * 128;
    const int n0 = blockIdx.y * 128;

    const uint32_t a_row = (lane & 15);
    const uint32_t a_col = (uint32_t)(lane >> 4) * 16;
    const uint32_t b_row = (lane & 7) + ((lane >> 4) << 3);
    const uint32_t b_col = (uint32_t)((lane >> 3) & 1) * 16;

    uint32_t a_off[4], b_off[2];
#pragma unroll
    for (int mt = 0; mt < 4; mt++)
        a_off[mt] = (uint32_t)(wm * 64 + mt * 16 + a_row) * RSB + a_col;
#pragma unroll
    for (int g = 0; g < 2; g++)
        b_off[g] = (uint32_t)(wn * 32 + g * 16 + b_row) * RSB + b_col;

    float acc[4][4][4];
#pragma unroll
    for (int mt = 0; mt < 4; mt++)
#pragma unroll
        for (int nf = 0; nf < 4; nf++)
#pragma unroll
            for (int e = 0; e < 4; e++) acc[mt][nf][e] = 0.f;

    gemm_load_stage(sb, 0, 0, m0, n0, tid);
    CP_COMMIT();

    for (int c = 0; c < NCHUNK; c++) {
        if (c + 1 < NCHUNK) {
            gemm_load_stage(sb, (c + 1) & 1, c + 1, m0, n0, tid);
            CP_COMMIT();
            CP_WAIT1();
        } else {
            CP_WAIT0();
        }
        __syncthreads();

        const uint32_t stg = sb + (c & 1) * STAGE_B;
#pragma unroll
        for (int ks = 0; ks < 2; ks++) {
            const uint32_t kb = (uint32_t)ks * 32;
            uint32_t ah[4][4];
#pragma unroll
            for (int mt = 0; mt < 4; mt++)
                ldx4(ah[mt], stg + OFF_AH + a_off[mt] + kb);
#pragma unroll
            for (int g = 0; g < 2; g++) {
                uint32_t bh[4], bl[4];
                ldx4(bh, stg + OFF_BH + b_off[g] + kb);
                ldx4(bl, stg + OFF_BL + b_off[g] + kb);
                // long independent chains (distance 8)
#pragma unroll
                for (int mt = 0; mt < 4; mt++)
                    mma16816(acc[mt][2 * g],     ah[mt], bh[0], bh[1]);
#pragma unroll
                for (int mt = 0; mt < 4; mt++)
                    mma16816(acc[mt][2 * g + 1], ah[mt], bh[2], bh[3]);
#pragma unroll
                for (int mt = 0; mt < 4; mt++)
                    mma16816(acc[mt][2 * g],     ah[mt], bl[0], bl[1]);
#pragma unroll
                for (int mt = 0; mt < 4; mt++)
                    mma16816(acc[mt][2 * g + 1], ah[mt], bl[2], bl[3]);
            }
        }
        __syncthreads();
    }

    const int gid = lane >> 2;
    const int tig = lane & 3;
#pragma unroll
    for (int mt = 0; mt < 4; mt++) {
        const int r0 = m0 + wm * 64 + mt * 16 + gid;
#pragma unroll
        for (int nf = 0; nf < 4; nf++) {
            const int col = n0 + wn * 32 + nf * 8 + 2 * tig;
            const float b0 = bias[col], b1 = bias[col + 1];
            float2 v0 = make_float2(acc[mt][nf][0] + b0, acc[mt][nf][1] + b1);
            float2 v1 = make_float2(acc[mt][nf][2] + b0, acc[mt][nf][3] + b1);
            *(float2*)(g_xp + (size_t)r0 * HD + col)       = v0;
            *(float2*)(g_xp + (size_t)(r0 + 8) * HD + col) = v1;
        }
    }
}

// =====================================================================
// K2: streaming LayerNorm (NO centering, NO transpose). One block per
// (h,b). Writes fp16 hi/lo in natural (l,d) layout + column sums +
// tile mean (centering folded into cov as rank-1 correction).
// =====================================================================
__global__ void __launch_bounds__(256) k_lnc(
    const float* __restrict__ g, const float* __restrict__ be)
{
    __shared__ float smh[8][128];
    __shared__ float smf[8][128];

    const int h = blockIdx.x >> 8;
    const int b = blockIdx.x & 255;
    const int tid  = threadIdx.x;
    const int warp = tid >> 5;
    const int lane = tid & 31;

    const float4 gv = *(const float4*)(g + lane * 4);
    const float4 bv = *(const float4*)(be + lane * 4);

    __half* dst_h = gHn_h + ((size_t)(h * B_ + b)) * LP * DH;
    __half* dst_l = gHn_l + ((size_t)(h * B_ + b)) * LP * DH;

    float sh0 = 0.f, sh1 = 0.f, sh2 = 0.f, sh3 = 0.f;
    float sf0 = 0.f, sf1 = 0.f, sf2 = 0.f, sf3 = 0.f;

    for (int l = warp; l < LP; l += 8) {
        const float* src = g_xp + ((size_t)(b * LP + l)) * HD + h * DH;
        float4 v = *(const float4*)(src + lane * 4);

        float s = v.x + v.y + v.z + v.w;
#pragma unroll
        for (int o = 16; o; o >>= 1) s += __shfl_xor_sync(0xffffffffu, s, o);
        const float mu = s * (1.0f / 128.0f);

        const float d0 = v.x - mu, d1 = v.y - mu, d2 = v.z - mu, d3 = v.w - mu;
        float sq = d0 * d0 + d1 * d1 + d2 * d2 + d3 * d3;
#pragma unroll
        for (int o = 16; o; o >>= 1) sq += __shfl_xor_sync(0xffffffffu, sq, o);
        const float rstd = rsqrtf(sq * (1.0f / 128.0f) + 1e-5f);

        const float o0 = d0 * rstd * gv.x + bv.x;
        const float o1 = d1 * rstd * gv.y + bv.y;
        const float o2 = d2 * rstd * gv.z + bv.z;
        const float o3 = d3 * rstd * gv.w + bv.w;

        const __half h0 = __float2half_rn(o0);
        const __half h1 = __float2half_rn(o1);
        const __half h2 = __float2half_rn(o2);
        const __half h3 = __float2half_rn(o3);
        __half2 hh01; hh01.x = h0; hh01.y = h1;
        __half2 hh23; hh23.x = h2; hh23.y = h3;
        __half2 ll01, ll23;
        ll01.x = __float2half_rn(o0 - __half2float(h0));
        ll01.y = __float2half_rn(o1 - __half2float(h1));
        ll23.x = __float2half_rn(o2 - __half2float(h2));
        ll23.y = __float2half_rn(o3 - __half2float(h3));

        const size_t ro = (size_t)l * DH + lane * 4;
        *(__half2*)(dst_h + ro)     = hh01;
        *(__half2*)(dst_h + ro + 2) = hh23;
        *(__half2*)(dst_l + ro)     = ll01;
        *(__half2*)(dst_l + ro + 2) = ll23;

        sh0 += __half2float(h0); sh1 += __half2float(h1);
        sh2 += __half2float(h2); sh3 += __half2float(h3);
        sf0 += o0; sf1 += o1; sf2 += o2; sf3 += o3;
    }
    smh[warp][lane * 4 + 0] = sh0; smh[warp][lane * 4 + 1] = sh1;
    smh[warp][lane * 4 + 2] = sh2; smh[warp][lane * 4 + 3] = sh3;
    smf[warp][lane * 4 + 0] = sf0; smf[warp][lane * 4 + 1] = sf1;
    smf[warp][lane * 4 + 2] = sf2; smf[warp][lane * 4 + 3] = sf3;
    __syncthreads();

    if (tid < 128) {
        float th = 0.f, tf = 0.f;
#pragma unroll
        for (int w = 0; w < 8; w++) { th += smh[w][tid]; tf += smf[w][tid]; }
        gSh[(size_t)(h * B_ + b) * DH + tid] = th;
        gSf[(size_t)(h * B_ + b) * DH + tid] = tf;
        smf[0][tid] = tf;
    }
    __syncthreads();
    if (tid < 32) {
        float t = smf[0][tid] + smf[0][tid + 32] + smf[0][tid + 64] + smf[0][tid + 96];
#pragma unroll
        for (int o = 16; o; o >>= 1) t += __shfl_xor_sync(0xffffffffu, t, o);
        if (tid == 0) gM[h * B_ + b] = t * (1.0f / (LP * DH));
    }
}

// =====================================================================
// K3: cov via fp16 mma with ldmatrix.trans on l-major tiles (no
// transpose needed). M = sum_l x1h[l,d]*x2[l,e]; centering applied as
// rank-1 correction; then column-L2 normalize; write NCHW.
// =====================================================================
#define CRS2   136                      // padded row stride (halves)
#define CRSB2  (CRS2 * 2)               // 272 B = 17*16B (conflict-free)
#define CTILE2 (208 * CRSB2)            // 56576 (208 k-rows incl. zero pad)
#define COV_SMEM (3 * CTILE2)           // 169,728

__global__ void __launch_bounds__(256) k_cov_mma()
{
    extern __shared__ char csm[];
    const uint32_t sb = smem_u32(csm);
    __shared__ float colsq[DH];
    __shared__ float s1s[DH];
    __shared__ float s2s[DH];

    const int p = blockIdx.x;
    const int b = blockIdx.y;
    const int tid  = threadIdx.x;
    const int wid  = tid >> 5;
    const int lane = tid & 31;
    const int wm = wid >> 1;              // 0..3 (m=d 32 each)
    const int wn = wid & 1;               // 0..1 (n=e 64 each)

    const __half* Asrc = gHn_h + ((size_t)(p * B_ + b)) * LP * DH;
    const __half* Bhs  = gHn_h + ((size_t)((p + 1) * B_ + b)) * LP * DH;
    const __half* Bls  = gHn_l + ((size_t)((p + 1) * B_ + b)) * LP * DH;

    const uint32_t tA = sb, tBh = sb + CTILE2, tBl = sb + 2 * CTILE2;

    // zero pad rows 196..207 (k padding) -- 12 rows x 17 uint4 x 3 tiles
    for (int i = tid; i < 3 * 12 * 17; i += 256) {
        const int tile = i / 204;
        const int rem  = i % 204;
        const int r    = rem / 17;
        const int c    = rem % 17;
        *(uint4*)(csm + (size_t)tile * CTILE2 + (196 + r) * CRSB2 + c * 16) =
            make_uint4(0u, 0u, 0u, 0u);
    }
    // load 196 rows x 128 halves per tile (16 cp16 per row)
    for (int t = tid; t < LP * 16; t += 256) {
        const int row = t >> 4;
        const int ch  = t & 15;
        const uint32_t doff = (uint32_t)row * CRSB2 + ch * 16;
        const size_t   goff = (size_t)row * DH + ch * 8;
        cp16(tA  + doff, Asrc + goff);
        cp16(tBh + doff, Bhs + goff);
        cp16(tBl + doff, Bls + goff);
    }
    CP_COMMIT();
    if (tid < DH) {
        colsq[tid] = 0.f;
        s1s[tid] = gSh[(size_t)(p * B_ + b) * DH + tid];
        s2s[tid] = gSf[(size_t)((p + 1) * B_ + b) * DH + tid];
    }
    CP_WAIT0();
    __syncthreads();

    // trans-ldmatrix address patterns (tiles are k-major: rows=l, cols=d/e)
    // A (m16k16):   row=(lane&7)+((lane>>4)<<3), colB=((lane>>3)&1)*16
    // B (n16k16):   row=(lane&7)+((lane>>3)&1)*8, colB=(lane>>4)*16
    const uint32_t ar = (lane & 7) + ((lane >> 4) << 3);
    const uint32_t ac = ((lane >> 3) & 1) * 16;
    const uint32_t br = (lane & 7) + (((lane >> 3) & 1) << 3);
    const uint32_t bc = (uint32_t)(lane >> 4) * 16;

    uint32_t a_off[2], b_off[4];
#pragma unroll
    for (int mt = 0; mt < 2; mt++)
        a_off[mt] = ar * CRSB2 + (uint32_t)(wm * 32 + mt * 16) * 2 + ac;
#pragma unroll
    for (int g = 0; g < 4; g++)
        b_off[g] = br * CRSB2 + (uint32_t)(wn * 64 + g * 16) * 2 + bc;

    float acc[2][8][4];
#pragma unroll
    for (int mt = 0; mt < 2; mt++)
#pragma unroll
        for (int nt = 0; nt < 8; nt++)
#pragma unroll
            for (int e = 0; e < 4; e++) acc[mt][nt][e] = 0.f;

#pragma unroll
    for (int ks = 0; ks < 13; ks++) {
        const uint32_t kb = (uint32_t)ks * 16 * CRSB2;
        uint32_t ah[2][4];
#pragma unroll
        for (int mt = 0; mt < 2; mt++)
            ldx4t(ah[mt], tA + a_off[mt] + kb);
#pragma unroll
        for (int g = 0; g < 4; g++) {
            uint32_t bh[4], bl[4];
            ldx4t(bh, tBh + b_off[g] + kb);
            ldx4t(bl, tBl + b_off[g] + kb);
#pragma unroll
            for (int mt = 0; mt < 2; mt++) {
                mma16816(acc[mt][2 * g],     ah[mt], bh[0], bh[1]);
                mma16816(acc[mt][2 * g],     ah[mt], bl[0], bl[1]);
                mma16816(acc[mt][2 * g + 1], ah[mt], bh[2], bh[3]);
                mma16816(acc[mt][2 * g + 1], ah[mt], bl[2], bl[3]);
            }
        }
    }

    // rank-1 centering correction:
    // cov = M - m1*s2f[e] - m2*s1h[d] + LP*m1*m2
    const float m1 = gM[p * B_ + b];
    const float m2 = gM[(p + 1) * B_ + b];
    const float c12 = (float)LP * m1 * m2;
    const int gid = lane >> 2;
    const int tig = lane & 3;
#pragma unroll
    for (int mt = 0; mt < 2; mt++) {
        const int d0 = wm * 32 + mt * 16 + gid;
        const float t1a = m2 * s1s[d0]     - c12;
        const float t1b = m2 * s1s[d0 + 8] - c12;
#pragma unroll
        for (int nt = 0; nt < 8; nt++) {
            const int e0 = wn * 64 + nt * 8 + 2 * tig;
            const float t2a = m1 * s2s[e0];
            const float t2b = m1 * s2s[e0 + 1];
            acc[mt][nt][0] -= t1a + t2a;
            acc[mt][nt][1] -= t1a + t2b;
            acc[mt][nt][2] -= t1b + t2a;
            acc[mt][nt][3] -= t1b + t2b;
        }
    }

    // column sum-of-squares per e
#pragma unroll
    for (int nt = 0; nt < 8; nt++) {
        float s0 = acc[0][nt][0] * acc[0][nt][0] + acc[0][nt][2] * acc[0][nt][2]
                 + acc[1][nt][0] * acc[1][nt][0] + acc[1][nt][2] * acc[1][nt][2];
        float s1 = acc[0][nt][1] * acc[0][nt][1] + acc[0][nt][3] * acc[0][nt][3]
                 + acc[1][nt][1] * acc[1][nt][1] + acc[1][nt][3] * acc[1][nt][3];
#pragma unroll
        for (int o = 4; o <= 16; o <<= 1) {
            s0 += __shfl_xor_sync(0xffffffffu, s0, o);
            s1 += __shfl_xor_sync(0xffffffffu, s1, o);
        }
        if (lane < 4) {
            const int col = wn * 64 + nt * 8 + 2 * lane;
            atomicAdd(&colsq[col], s0);
            atomicAdd(&colsq[col + 1], s1);
        }
    }
    __syncthreads();

    float* outb = g_cov + ((size_t)(b * 3 + p)) * (DH * DH);
#pragma unroll
    for (int nt = 0; nt < 8; nt++) {
        const int col = wn * 64 + nt * 8 + 2 * tig;
        const float i0 = 1.0f / fmaxf(sqrtf(colsq[col]),     (float)LP * 1e-12f);
        const float i1 = 1.0f / fmaxf(sqrtf(colsq[col + 1]), (float)LP * 1e-12f);
#pragma unroll
        for (int mt = 0; mt < 2; mt++) {
            const int r0 = wm * 32 + mt * 16 + gid;
            float2 v0 = make_float2(acc[mt][nt][0] * i0, acc[mt][nt][1] * i1);
            float2 v1 = make_float2(acc[mt][nt][2] * i0, acc[mt][nt][3] * i1);
            *(float2*)(outb + (size_t)r0 * DH + col)       = v0;
            *(float2*)(outb + (size_t)(r0 + 8) * DH + col) = v1;
        }
    }
}

// =====================================================================
// K4: fused conv1 -> GELU -> conv2, cov staged in smem (2 y-phases)
// =====================================================================
#define CONV_CS_B  (3 * 66 * 128 * 4)
#define CONV_SMEM  (CONV_CS_B + 3 * 3969 * 4)  // 149,004

__global__ void __launch_bounds__(256) k_conv(
    const float* __restrict__ w1, const float* __restrict__ w2)
{
    extern __shared__ char cvsm[];
    float* cs = (float*)cvsm;
    float* z1 = (float*)(cvsm + CONV_CS_B);
    __shared__ float w1s[81];
    __shared__ float w2s[81];

    const int b = blockIdx.x;
    const int tid = threadIdx.x;
    if (tid < 81) { w1s[tid] = w1[tid]; w2s[tid] = w2[tid]; }

    const float* cb = g_cov + (size_t)b * 3 * DH * DH;

#pragma unroll 1
    for (int ph = 0; ph < 2; ph++) {
        const int r0 = ph * 64;
        const int nr = ph ? 64 : 66;
        const int y0 = ph ? 32 : 0;
        const int ny = ph ? 31 : 32;
        __syncthreads();
        for (int i = tid; i < 3 * nr * 32; i += 256) {
            const int c  = i / (nr * 32);
            const int rr = (i / 32) % nr;
            const int q  = i % 32;
            *(float4*)(cs + (c * 66 + rr) * 128 + q * 4) =
                *(const float4*)(cb + (size_t)c * (DH * DH) + (r0 + rr) * DH + q * 4);
        }
        __syncthreads();
        for (int idx = tid; idx < 3 * ny * 63; idx += 256) {
            const int c = idx / (ny * 63);
            const int r = idx % (ny * 63);
            const int y = y0 + r / 63;
            const int x = r % 63;
            float s = 0.f;
#pragma unroll
            for (int ci = 0; ci < 3; ci++)
#pragma unroll
                for (int ky = 0; ky < 3; ky++)
#pragma unroll
                    for (int kx = 0; kx < 3; kx++)
                        s += cs[(ci * 66 + (2 * y + ky - r0)) * 128 + 2 * x + kx]
                           * w1s[((c * 3 + ci) * 3 + ky) * 3 + kx];
            s = 0.5f * s * (1.0f + erff(s * 0.70710678118654752f));
            z1[c * 3969 + y * 63 + x] = s;
        }
    }
    __syncthreads();

    for (int idx = tid; idx < FLATN; idx += 256) {
        const int c = idx / 961;
        const int r = idx % 961;
        const int y = r / 31, x = r % 31;
        float s = 0.f;
#pragma unroll
        for (int ci = 0; ci < 3; ci++)
#pragma unroll
            for (int ky = 0; ky < 3; ky++)
#pragma unroll
                for (int kx = 0; kx < 3; kx++)
                    s += z1[ci * 3969 + (2 * y + ky) * 63 + (2 * x + kx)]
                       * w2s[((c * 3 + ci) * 3 + ky) * 3 + kx];
        g_flat[(size_t)b * FLATN + idx] = s;
    }
}

// =====================================================================
// K5: classifier head
// =====================================================================
__global__ void __launch_bounds__(256) k_head(
    const float* __restrict__ cls, const float* __restrict__ w1,
    const float* __restrict__ b1, const float* __restrict__ w2,
    const float* __restrict__ b2, float* __restrict__ out)
{
    const int n  = blockIdx.x * 256 + threadIdx.x;
    const int b0 = blockIdx.y * 8;
    const bool ok = (n < NC);

    float acc[8];
#pragma unroll
    for (int i = 0; i < 8; i++) acc[i] = 0.f;

    __shared__ float As[8][64];

    for (int k0 = 0; k0 < D_; k0 += 64) {
        for (int q = threadIdx.x; q < 512; q += 256) {
            const int bi = q >> 6, kk = q & 63;
            As[bi][kk] = cls[(size_t)(b0 + bi) * D_ + k0 + kk];
        }
        __syncthreads();
        if (ok) {
#pragma unroll 8
            for (int kk = 0; kk < 64; kk++) {
                const float w = w1[(size_t)(k0 + kk) * NC + n];
#pragma unroll
                for (int bi = 0; bi < 8; bi++) acc[bi] += As[bi][kk] * w;
            }
        }
        __syncthreads();
    }

    for (int c = 0; c < 45; c++) {
        const int k0 = c * 64;
        for (int q = threadIdx.x; q < 512; q += 256) {
            const int bi = q >> 6, kk = q & 63;
            As[bi][kk] = g_flat[(size_t)(b0 + bi) * FLATN + k0 + kk];
        }
        __syncthreads();
        if (ok) {
#pragma unroll 8
            for (int kk = 0; kk < 64; kk++) {
                const float w = w2[(size_t)(k0 + kk) * NC + n];
#pragma unroll
                for (int bi = 0; bi < 8; bi++) acc[bi] += As[bi][kk] * w;
            }
        }
        __syncthreads();
    }
    {
        const int k0 = 2880;
        if (threadIdx.x < 8 * 3) {
            const int bi = threadIdx.x / 3, kk = threadIdx.x % 3;
            As[bi][kk] = g_flat[(size_t)(b0 + bi) * FLATN + k0 + kk];
        }
        __syncthreads();
        if (ok) {
            for (int kk = 0; kk < 3; kk++) {
                const float w = w2[(size_t)(k0 + kk) * NC + n];
#pragma unroll
                for (int bi = 0; bi < 8; bi++) acc[bi] += As[bi][kk] * w;
            }
        }
    }

    if (ok) {
        const float bb = b1[n] + b2[n];
#pragma unroll
        for (int bi = 0; bi < 8; bi++)
            out[(size_t)(b0 + bi) * NC + n] = (acc[bi] + bb) * 0.5f;
    }
}

// =====================================================================
// launch
// =====================================================================
extern "C" void kernel_launch(void* const* d_in, const int* in_sizes, int n_in,
                              void* d_out, int out_size)
{
    const float* cls_token = (const float*)d_in[0];
    const float* x         = (const float*)d_in[1];
    const float* proj_w    = (const float*)d_in[2];
    const float* proj_b    = (const float*)d_in[3];
    const float* ln_g      = (const float*)d_in[4];
    const float* ln_b      = (const float*)d_in[5];
    const float* conv1_w   = (const float*)d_in[6];
    const float* conv2_w   = (const float*)d_in[7];
    const float* cls1_w    = (const float*)d_in[8];
    const float* cls1_b    = (const float*)d_in[9];
    const float* cls2_w    = (const float*)d_in[10];
    const float* cls2_b    = (const float*)d_in[11];
    float* out = (float*)d_out;

    cudaFuncSetAttribute(k_gemm_mma,
                         cudaFuncAttributeMaxDynamicSharedMemorySize, GEMM_SMEM);
    cudaFuncSetAttribute(k_cov_mma,
                         cudaFuncAttributeMaxDynamicSharedMemorySize, COV_SMEM);
    cudaFuncSetAttribute(k_conv,
                         cudaFuncAttributeMaxDynamicSharedMemorySize, CONV_SMEM);

    k_prep<<<2432, 256>>>(x, proj_w);                             // 0
    k_gemm_mma<<<dim3(392, 4), 256, GEMM_SMEM>>>(proj_b);         // 1
    k_lnc<<<NH * B_, 256>>>(ln_g, ln_b);                          // 2
    k_cov_mma<<<dim3(3, B_), 256, COV_SMEM>>>();                  // 3 <- ncu probe
    k_conv<<<B_, 256, CONV_SMEM>>>(conv1_w, conv2_w);             // 4
    k_head<<<dim3(4, 32), 256>>>(cls_token, cls1_w, cls1_b, cls2_w, cls2_b, out);
}

// round 10
// speedup vs baseline: 2.1240x; 1.9672x over previous
#include <cuda_runtime.h>
#include <cuda_bf16.h>
#include <cuda_fp16.h>
#include <math.h>
#include <stdint.h>

// ---------------- problem constants ----------------
#define B_    256
#define L_    197
#define LP    196
#define D_    768
#define HD    512
#define DH    128
#define NH    4
#define NC    1000
#define FLATN 2883   // 3*31*31
#define FPAD  2944   // flat padded to multiple of 32
#define NPAD  1024   // classifier N padded
#define HK_CLS_CHUNKS  24          // 768/32
#define HK_CHUNKS      116         // 24 + 92
#define HK_SPLIT       29          // chunks per k-split (116/4)

// ---------------- scratch (static __device__, no allocation) ----------------
__device__ float g_xp[(size_t)B_ * LP * HD];          // 50176 x 512
__device__ float g_cov[(size_t)B_ * 3 * DH * DH];     // (b,p,d,e) NCHW

// fp16 buffers for tensor-core projection GEMM
__device__ __half gA_h[(size_t)B_ * LP * D_];    // [50176,768]
__device__ __half gWt_h[(size_t)HD * D_];        // [512,768]  W^T hi
__device__ __half gWt_l[(size_t)HD * D_];        // [512,768]  W^T lo

// LN output (UNcentered), fp16 hi/lo, natural layout (h,b, l=196, d=128)
__device__ __half gHn_h[(size_t)NH * B_ * LP * DH];
__device__ __half gHn_l[(size_t)NH * B_ * LP * DH];
__device__ float gSh[(size_t)NH * B_ * DH];   // sum_l hi(hn)
__device__ float gSf[(size_t)NH * B_ * DH];   // sum_l hn (float)
__device__ float gM [(size_t)NH * B_];        // tile mean

// classifier-head fp16 buffers
__device__ __half gW1_h[(size_t)D_ * NPAD];      // [768,1024]
__device__ __half gW1_l[(size_t)D_ * NPAD];
__device__ __half gW2_h[(size_t)FPAD * NPAD];    // [2944,1024]
__device__ __half gW2_l[(size_t)FPAD * NPAD];
__device__ __half gCls_h[(size_t)B_ * D_];       // [256,768]
__device__ __half gCls_l[(size_t)B_ * D_];
__device__ __half gF_h[(size_t)B_ * FPAD];       // [256,2944]
__device__ __half gF_l[(size_t)B_ * FPAD];

// ---------------- baseline-PTX helpers ----------------
__device__ __forceinline__ uint32_t smem_u32(const void* p) {
    uint32_t a;
    asm("{ .reg .u64 t; cvta.to.shared.u64 t, %1; cvt.u32.u64 %0, t; }"
        : "=r"(a) : "l"(p));
    return a;
}
__device__ __forceinline__ void cp16(uint32_t dst, const void* src) {
    asm volatile("cp.async.ca.shared.global [%0], [%1], 16;"
                 :: "r"(dst), "l"(src) : "memory");
}
#define CP_COMMIT() asm volatile("cp.async.commit_group;" ::: "memory")
#define CP_WAIT0()  asm volatile("cp.async.wait_group 0;" ::: "memory")
#define CP_WAIT1()  asm volatile("cp.async.wait_group 1;" ::: "memory")

__device__ __forceinline__ void ldx4(uint32_t* r, uint32_t addr) {
    asm volatile("ldmatrix.sync.aligned.m8n8.x4.shared.b16 {%0,%1,%2,%3}, [%4];"
                 : "=r"(r[0]), "=r"(r[1]), "=r"(r[2]), "=r"(r[3]) : "r"(addr));
}
__device__ __forceinline__ void ldx4t(uint32_t* r, uint32_t addr) {
    asm volatile("ldmatrix.sync.aligned.m8n8.x4.trans.shared.b16 {%0,%1,%2,%3}, [%4];"
                 : "=r"(r[0]), "=r"(r[1]), "=r"(r[2]), "=r"(r[3]) : "r"(addr));
}
__device__ __forceinline__ void mma16816(float* c, const uint32_t* a,
                                         uint32_t b0, uint32_t b1) {
    asm volatile(
        "mma.sync.aligned.m16n8k16.row.col.f32.f16.f16.f32 "
        "{%0,%1,%2,%3}, {%4,%5,%6,%7}, {%8,%9}, {%0,%1,%2,%3};"
        : "+f"(c[0]), "+f"(c[1]), "+f"(c[2]), "+f"(c[3])
        : "r"(a[0]), "r"(a[1]), "r"(a[2]), "r"(a[3]), "r"(b0), "r"(b1));
}

// =====================================================================
// K0a: round x[:,1:,:] to fp16  [50176,768]
// =====================================================================
__global__ void __launch_bounds__(256) k_convA(const float* __restrict__ X)
{
    const int total = B_ * LP * (D_ / 4);
    for (int i = blockIdx.x * blockDim.x + threadIdx.x; i < total;
         i += gridDim.x * blockDim.x) {
        const int m  = i / (D_ / 4);
        const int k4 = i - m * (D_ / 4);
        const int b  = m / LP;
        const int l  = m - b * LP + 1;
        float4 v = *(const float4*)(X + ((size_t)(b * L_ + l)) * D_ + k4 * 4);
        __half2 h01, h23;
        h01.x = __float2half_rn(v.x); h01.y = __float2half_rn(v.y);
        h23.x = __float2half_rn(v.z); h23.y = __float2half_rn(v.w);
        ((__half2*)gA_h)[(size_t)i * 2]     = h01;
        ((__half2*)gA_h)[(size_t)i * 2 + 1] = h23;
    }
}

// =====================================================================
// K0b: W [768,512] -> W^T split fp16 hi/lo [512,768]
// =====================================================================
__global__ void __launch_bounds__(256) k_convW(const float* __restrict__ W)
{
    __shared__ float t[32][33];
    const int nb = blockIdx.x * 32;
    const int kb = blockIdx.y * 32;
    const int tx = threadIdx.x & 31, ty = threadIdx.x >> 5;
#pragma unroll
    for (int r = 0; r < 32; r += 8)
        t[ty + r][tx] = W[(size_t)(kb + ty + r) * HD + nb + tx];
    __syncthreads();
#pragma unroll
    for (int r = 0; r < 32; r += 8) {
        const float v = t[tx][ty + r];
        const __half h  = __float2half_rn(v);
        const __half lo = __float2half_rn(v - __half2float(h));
        const size_t o = (size_t)(nb + ty + r) * D_ + kb + tx;
        gWt_h[o] = h;
        gWt_l[o] = lo;
    }
}

// =====================================================================
// K0c: head-weight conversions + out init
//  w1 [768,1000]->[768,1024] h/l ; w2 [2883,1000]->[2944,1024] h/l (pad 0)
//  cls [256,768] h/l ; out[b][n] = 0.5*(b1[n]+b2[n])
// =====================================================================
#define CH_S1 (D_ * NPAD)                 // 786432
#define CH_S2 ((size_t)FPAD * NPAD)       // 3014656
#define CH_S3 (B_ * D_)                   // 196608
#define CH_S4 (B_ * NC)                   // 256000
#define CH_TOTAL (CH_S1 + CH_S2 + CH_S3 + CH_S4)

__global__ void __launch_bounds__(256) k_convH(
    const float* __restrict__ w1, const float* __restrict__ w2,
    const float* __restrict__ cls, const float* __restrict__ b1,
    const float* __restrict__ b2, float* __restrict__ out)
{
    for (size_t i = (size_t)blockIdx.x * 256 + threadIdx.x; i < CH_TOTAL;
         i += (size_t)gridDim.x * 256) {
        if (i < CH_S1) {
            const int r = (int)(i >> 10), c = (int)(i & 1023);
            float v = (c < NC) ? w1[(size_t)r * NC + c] : 0.f;
            const __half h = __float2half_rn(v);
            gW1_h[i] = h;
            gW1_l[i] = __float2half_rn(v - __half2float(h));
        } else if (i < CH_S1 + CH_S2) {
            const size_t j = i - CH_S1;
            const int r = (int)(j >> 10), c = (int)(j & 1023);
            float v = (r < FLATN && c < NC) ? w2[(size_t)r * NC + c] : 0.f;
            const __half h = __float2half_rn(v);
            gW2_h[j] = h;
            gW2_l[j] = __float2half_rn(v - __half2float(h));
        } else if (i < CH_S1 + CH_S2 + CH_S3) {
            const size_t j = i - CH_S1 - CH_S2;
            float v = cls[j];
            const __half h = __float2half_rn(v);
            gCls_h[j] = h;
            gCls_l[j] = __float2half_rn(v - __half2float(h));
        } else {
            const size_t j = i - CH_S1 - CH_S2 - CH_S3;
            const int n = (int)(j % NC);
            out[j] = 0.5f * (b1[n] + b2[n]);
        }
    }
}

// =====================================================================
// K1: warp-mma fp16 2-pass GEMM: xp = A_h @ (B_h + B_l)   <- ncu probe
// =====================================================================
#define RSB      80
#define TILE_B   (128 * RSB)
#define OFF_AH   0
#define OFF_BH   (1 * TILE_B)
#define OFF_BL   (2 * TILE_B)
#define STAGE_B  (3 * TILE_B)          // 30720
#define GEMM_SMEM (2 * STAGE_B)        // 61440
#define NCHUNK   (D_ / 32)             // 24

__device__ __forceinline__ void gemm_load_stage(
    uint32_t sb, int buf, int c, int m0, int n0, int tid)
{
    const int k0 = c * 32;
    const uint32_t stg = sb + buf * STAGE_B;
#pragma unroll
    for (int q = 0; q < 2; q++) {
        const int ch  = q * 256 + tid;
        const int row = ch >> 2;
        const int cc  = ch & 3;
        const uint32_t doff = (uint32_t)row * RSB + cc * 16;
        const size_t ga = (size_t)(m0 + row) * D_ + k0 + cc * 8;
        const size_t gb = (size_t)(n0 + row) * D_ + k0 + cc * 8;
        cp16(stg + OFF_AH + doff, gA_h + ga);
        cp16(stg + OFF_BH + doff, gWt_h + gb);
        cp16(stg + OFF_BL + doff, gWt_l + gb);
    }
}

__global__ void __launch_bounds__(256) k_gemm_mma(const float* __restrict__ bias)
{
    extern __shared__ char smem[];
    const uint32_t sb = smem_u32(smem);
    const int tid  = threadIdx.x;
    const int wid  = tid >> 5;
    const int lane = tid & 31;
    const int wm = wid >> 2;              // 0..1 (m 64 each)
    const int wn = wid & 3;               // 0..3 (n 32 each)
    const int m0 = blockIdx.x * 128;
    const int n0 = blockIdx.y * 128;

    const uint32_t a_row = (lane & 15);
    const uint32_t a_col = (uint32_t)(lane >> 4) * 16;
    const uint32_t b_row = (lane & 7) + ((lane >> 4) << 3);
    const uint32_t b_col = (uint32_t)((lane >> 3) & 1) * 16;

    uint32_t a_off[4], b_off[2];
#pragma unroll
    for (int mt = 0; mt < 4; mt++)
        a_off[mt] = (uint32_t)(wm * 64 + mt * 16 + a_row) * RSB + a_col;
#pragma unroll
    for (int g = 0; g < 2; g++)
        b_off[g] = (uint32_t)(wn * 32 + g * 16 + b_row) * RSB + b_col;

    float acc[4][4][4];
#pragma unroll
    for (int mt = 0; mt < 4; mt++)
#pragma unroll
        for (int nf = 0; nf < 4; nf++)
#pragma unroll
            for (int e = 0; e < 4; e++) acc[mt][nf][e] = 0.f;

    gemm_load_stage(sb, 0, 0, m0, n0, tid);
    CP_COMMIT();

    for (int c = 0; c < NCHUNK; c++) {
        if (c + 1 < NCHUNK) {
            gemm_load_stage(sb, (c + 1) & 1, c + 1, m0, n0, tid);
            CP_COMMIT();
            CP_WAIT1();
        } else {
            CP_WAIT0();
        }
        __syncthreads();

        const uint32_t stg = sb + (c & 1) * STAGE_B;
#pragma unroll
        for (int ks = 0; ks < 2; ks++) {
            const uint32_t kb = (uint32_t)ks * 32;
            uint32_t ah[4][4];
#pragma unroll
            for (int mt = 0; mt < 4; mt++)
                ldx4(ah[mt], stg + OFF_AH + a_off[mt] + kb);
#pragma unroll
            for (int g = 0; g < 2; g++) {
                uint32_t bh[4], bl[4];
                ldx4(bh, stg + OFF_BH + b_off[g] + kb);
                ldx4(bl, stg + OFF_BL + b_off[g] + kb);
#pragma unroll
                for (int mt = 0; mt < 4; mt++)
                    mma16816(acc[mt][2 * g],     ah[mt], bh[0], bh[1]);
#pragma unroll
                for (int mt = 0; mt < 4; mt++)
                    mma16816(acc[mt][2 * g + 1], ah[mt], bh[2], bh[3]);
#pragma unroll
                for (int mt = 0; mt < 4; mt++)
                    mma16816(acc[mt][2 * g],     ah[mt], bl[0], bl[1]);
#pragma unroll
                for (int mt = 0; mt < 4; mt++)
                    mma16816(acc[mt][2 * g + 1], ah[mt], bl[2], bl[3]);
            }
        }
        __syncthreads();
    }

    const int gid = lane >> 2;
    const int tig = lane & 3;
#pragma unroll
    for (int mt = 0; mt < 4; mt++) {
        const int r0 = m0 + wm * 64 + mt * 16 + gid;
#pragma unroll
        for (int nf = 0; nf < 4; nf++) {
            const int col = n0 + wn * 32 + nf * 8 + 2 * tig;
            const float b0 = bias[col], b1v = bias[col + 1];
            float2 v0 = make_float2(acc[mt][nf][0] + b0, acc[mt][nf][1] + b1v);
            float2 v1 = make_float2(acc[mt][nf][2] + b0, acc[mt][nf][3] + b1v);
            *(float2*)(g_xp + (size_t)r0 * HD + col)       = v0;
            *(float2*)(g_xp + (size_t)(r0 + 8) * HD + col) = v1;
        }
    }
}

// =====================================================================
// K2: streaming LayerNorm (no centering/transpose) + column sums + mean
// =====================================================================
__global__ void __launch_bounds__(256) k_lnc(
    const float* __restrict__ g, const float* __restrict__ be)
{
    __shared__ float smh[8][128];
    __shared__ float smf[8][128];

    const int h = blockIdx.x >> 8;
    const int b = blockIdx.x & 255;
    const int tid  = threadIdx.x;
    const int warp = tid >> 5;
    const int lane = tid & 31;

    const float4 gv = *(const float4*)(g + lane * 4);
    const float4 bv = *(const float4*)(be + lane * 4);

    __half* dst_h = gHn_h + ((size_t)(h * B_ + b)) * LP * DH;
    __half* dst_l = gHn_l + ((size_t)(h * B_ + b)) * LP * DH;

    float sh0 = 0.f, sh1 = 0.f, sh2 = 0.f, sh3 = 0.f;
    float sf0 = 0.f, sf1 = 0.f, sf2 = 0.f, sf3 = 0.f;

    for (int l = warp; l < LP; l += 8) {
        const float* src = g_xp + ((size_t)(b * LP + l)) * HD + h * DH;
        float4 v = *(const float4*)(src + lane * 4);

        float s = v.x + v.y + v.z + v.w;
#pragma unroll
        for (int o = 16; o; o >>= 1) s += __shfl_xor_sync(0xffffffffu, s, o);
        const float mu = s * (1.0f / 128.0f);

        const float d0 = v.x - mu, d1 = v.y - mu, d2 = v.z - mu, d3 = v.w - mu;
        float sq = d0 * d0 + d1 * d1 + d2 * d2 + d3 * d3;
#pragma unroll
        for (int o = 16; o; o >>= 1) sq += __shfl_xor_sync(0xffffffffu, sq, o);
        const float rstd = rsqrtf(sq * (1.0f / 128.0f) + 1e-5f);

        const float o0 = d0 * rstd * gv.x + bv.x;
        const float o1 = d1 * rstd * gv.y + bv.y;
        const float o2 = d2 * rstd * gv.z + bv.z;
        const float o3 = d3 * rstd * gv.w + bv.w;

        const __half h0 = __float2half_rn(o0);
        const __half h1 = __float2half_rn(o1);
        const __half h2 = __float2half_rn(o2);
        const __half h3 = __float2half_rn(o3);
        __half2 hh01; hh01.x = h0; hh01.y = h1;
        __half2 hh23; hh23.x = h2; hh23.y = h3;
        __half2 ll01, ll23;
        ll01.x = __float2half_rn(o0 - __half2float(h0));
        ll01.y = __float2half_rn(o1 - __half2float(h1));
        ll23.x = __float2half_rn(o2 - __half2float(h2));
        ll23.y = __float2half_rn(o3 - __half2float(h3));

        const size_t ro = (size_t)l * DH + lane * 4;
        *(__half2*)(dst_h + ro)     = hh01;
        *(__half2*)(dst_h + ro + 2) = hh23;
        *(__half2*)(dst_l + ro)     = ll01;
        *(__half2*)(dst_l + ro + 2) = ll23;

        sh0 += __half2float(h0); sh1 += __half2float(h1);
        sh2 += __half2float(h2); sh3 += __half2float(h3);
        sf0 += o0; sf1 += o1; sf2 += o2; sf3 += o3;
    }
    smh[warp][lane * 4 + 0] = sh0; smh[warp][lane * 4 + 1] = sh1;
    smh[warp][lane * 4 + 2] = sh2; smh[warp][lane * 4 + 3] = sh3;
    smf[warp][lane * 4 + 0] = sf0; smf[warp][lane * 4 + 1] = sf1;
    smf[warp][lane * 4 + 2] = sf2; smf[warp][lane * 4 + 3] = sf3;
    __syncthreads();

    if (tid < 128) {
        float th = 0.f, tf = 0.f;
#pragma unroll
        for (int w = 0; w < 8; w++) { th += smh[w][tid]; tf += smf[w][tid]; }
        gSh[(size_t)(h * B_ + b) * DH + tid] = th;
        gSf[(size_t)(h * B_ + b) * DH + tid] = tf;
        smf[0][tid] = tf;
    }
    __syncthreads();
    if (tid < 32) {
        float t = smf[0][tid] + smf[0][tid + 32] + smf[0][tid + 64] + smf[0][tid + 96];
#pragma unroll
        for (int o = 16; o; o >>= 1) t += __shfl_xor_sync(0xffffffffu, t, o);
        if (tid == 0) gM[h * B_ + b] = t * (1.0f / (LP * DH));
    }
}

// =====================================================================
// K3: cov via fp16 mma, trans-ldmatrix, rank-1 centering + L2 norm
// =====================================================================
#define CRS2   136
#define CRSB2  (CRS2 * 2)               // 272 B
#define CTILE2 (208 * CRSB2)            // 56576
#define COV_SMEM (3 * CTILE2)           // 169,728

__global__ void __launch_bounds__(256) k_cov_mma()
{
    extern __shared__ char csm[];
    const uint32_t sb = smem_u32(csm);
    __shared__ float colsq[DH];
    __shared__ float s1s[DH];
    __shared__ float s2s[DH];

    const int p = blockIdx.x;
    const int b = blockIdx.y;
    const int tid  = threadIdx.x;
    const int wid  = tid >> 5;
    const int lane = tid & 31;
    const int wm = wid >> 1;
    const int wn = wid & 1;

    const __half* Asrc = gHn_h + ((size_t)(p * B_ + b)) * LP * DH;
    const __half* Bhs  = gHn_h + ((size_t)((p + 1) * B_ + b)) * LP * DH;
    const __half* Bls  = gHn_l + ((size_t)((p + 1) * B_ + b)) * LP * DH;

    const uint32_t tA = sb, tBh = sb + CTILE2, tBl = sb + 2 * CTILE2;

    for (int i = tid; i < 3 * 12 * 17; i += 256) {
        const int tile = i / 204;
        const int rem  = i % 204;
        const int r    = rem / 17;
        const int c    = rem % 17;
        *(uint4*)(csm + (size_t)tile * CTILE2 + (196 + r) * CRSB2 + c * 16) =
            make_uint4(0u, 0u, 0u, 0u);
    }
    for (int t = tid; t < LP * 16; t += 256) {
        const int row = t >> 4;
        const int ch  = t & 15;
        const uint32_t doff = (uint32_t)row * CRSB2 + ch * 16;
        const size_t   goff = (size_t)row * DH + ch * 8;
        cp16(tA  + doff, Asrc + goff);
        cp16(tBh + doff, Bhs + goff);
        cp16(tBl + doff, Bls + goff);
    }
    CP_COMMIT();
    if (tid < DH) {
        colsq[tid] = 0.f;
        s1s[tid] = gSh[(size_t)(p * B_ + b) * DH + tid];
        s2s[tid] = gSf[(size_t)((p + 1) * B_ + b) * DH + tid];
    }
    CP_WAIT0();
    __syncthreads();

    const uint32_t ar = (lane & 7) + ((lane >> 4) << 3);
    const uint32_t ac = ((lane >> 3) & 1) * 16;
    const uint32_t br = (lane & 7) + (((lane >> 3) & 1) << 3);
    const uint32_t bc = (uint32_t)(lane >> 4) * 16;

    uint32_t a_off[2], b_off[4];
#pragma unroll
    for (int mt = 0; mt < 2; mt++)
        a_off[mt] = ar * CRSB2 + (uint32_t)(wm * 32 + mt * 16) * 2 + ac;
#pragma unroll
    for (int g = 0; g < 4; g++)
        b_off[g] = br * CRSB2 + (uint32_t)(wn * 64 + g * 16) * 2 + bc;

    float acc[2][8][4];
#pragma unroll
    for (int mt = 0; mt < 2; mt++)
#pragma unroll
        for (int nt = 0; nt < 8; nt++)
#pragma unroll
            for (int e = 0; e < 4; e++) acc[mt][nt][e] = 0.f;

#pragma unroll
    for (int ks = 0; ks < 13; ks++) {
        const uint32_t kb = (uint32_t)ks * 16 * CRSB2;
        uint32_t ah[2][4];
#pragma unroll
        for (int mt = 0; mt < 2; mt++)
            ldx4t(ah[mt], tA + a_off[mt] + kb);
#pragma unroll
        for (int g = 0; g < 4; g++) {
            uint32_t bh[4], bl[4];
            ldx4t(bh, tBh + b_off[g] + kb);
            ldx4t(bl, tBl + b_off[g] + kb);
#pragma unroll
            for (int mt = 0; mt < 2; mt++) {
                mma16816(acc[mt][2 * g],     ah[mt], bh[0], bh[1]);
                mma16816(acc[mt][2 * g],     ah[mt], bl[0], bl[1]);
                mma16816(acc[mt][2 * g + 1], ah[mt], bh[2], bh[3]);
                mma16816(acc[mt][2 * g + 1], ah[mt], bl[2], bl[3]);
            }
        }
    }

    const float m1 = gM[p * B_ + b];
    const float m2 = gM[(p + 1) * B_ + b];
    const float c12 = (float)LP * m1 * m2;
    const int gid = lane >> 2;
    const int tig = lane & 3;
#pragma unroll
    for (int mt = 0; mt < 2; mt++) {
        const int d0 = wm * 32 + mt * 16 + gid;
        const float t1a = m2 * s1s[d0]     - c12;
        const float t1b = m2 * s1s[d0 + 8] - c12;
#pragma unroll
        for (int nt = 0; nt < 8; nt++) {
            const int e0 = wn * 64 + nt * 8 + 2 * tig;
            const float t2a = m1 * s2s[e0];
            const float t2b = m1 * s2s[e0 + 1];
            acc[mt][nt][0] -= t1a + t2a;
            acc[mt][nt][1] -= t1a + t2b;
            acc[mt][nt][2] -= t1b + t2a;
            acc[mt][nt][3] -= t1b + t2b;
        }
    }

#pragma unroll
    for (int nt = 0; nt < 8; nt++) {
        float s0 = acc[0][nt][0] * acc[0][nt][0] + acc[0][nt][2] * acc[0][nt][2]
                 + acc[1][nt][0] * acc[1][nt][0] + acc[1][nt][2] * acc[1][nt][2];
        float s1 = acc[0][nt][1] * acc[0][nt][1] + acc[0][nt][3] * acc[0][nt][3]
                 + acc[1][nt][1] * acc[1][nt][1] + acc[1][nt][3] * acc[1][nt][3];
#pragma unroll
        for (int o = 4; o <= 16; o <<= 1) {
            s0 += __shfl_xor_sync(0xffffffffu, s0, o);
            s1 += __shfl_xor_sync(0xffffffffu, s1, o);
        }
        if (lane < 4) {
            const int col = wn * 64 + nt * 8 + 2 * lane;
            atomicAdd(&colsq[col], s0);
            atomicAdd(&colsq[col + 1], s1);
        }
    }
    __syncthreads();

    float* outb = g_cov + ((size_t)(b * 3 + p)) * (DH * DH);
#pragma unroll
    for (int nt = 0; nt < 8; nt++) {
        const int col = wn * 64 + nt * 8 + 2 * tig;
        const float i0 = 1.0f / fmaxf(sqrtf(colsq[col]),     (float)LP * 1e-12f);
        const float i1 = 1.0f / fmaxf(sqrtf(colsq[col + 1]), (float)LP * 1e-12f);
#pragma unroll
        for (int mt = 0; mt < 2; mt++) {
            const int r0 = wm * 32 + mt * 16 + gid;
            float2 v0 = make_float2(acc[mt][nt][0] * i0, acc[mt][nt][1] * i1);
            float2 v1 = make_float2(acc[mt][nt][2] * i0, acc[mt][nt][3] * i1);
            *(float2*)(outb + (size_t)r0 * DH + col)       = v0;
            *(float2*)(outb + (size_t)(r0 + 8) * DH + col) = v1;
        }
    }
}

// =====================================================================
// K4: fused conv1 -> GELU -> conv2 ; emits flat as fp16 hi/lo (padded)
// =====================================================================
#define CONV_CS_B  (3 * 66 * 128 * 4)
#define CONV_SMEM  (CONV_CS_B + 3 * 3969 * 4)  // 149,004

__global__ void __launch_bounds__(256) k_conv(
    const float* __restrict__ w1, const float* __restrict__ w2)
{
    extern __shared__ char cvsm[];
    float* cs = (float*)cvsm;
    float* z1 = (float*)(cvsm + CONV_CS_B);
    __shared__ float w1s[81];
    __shared__ float w2s[81];

    const int b = blockIdx.x;
    const int tid = threadIdx.x;
    if (tid < 81) { w1s[tid] = w1[tid]; w2s[tid] = w2[tid]; }

    const float* cb = g_cov + (size_t)b * 3 * DH * DH;

#pragma unroll 1
    for (int ph = 0; ph < 2; ph++) {
        const int r0 = ph * 64;
        const int nr = ph ? 64 : 66;
        const int y0 = ph ? 32 : 0;
        const int ny = ph ? 31 : 32;
        __syncthreads();
        for (int i = tid; i < 3 * nr * 32; i += 256) {
            const int c  = i / (nr * 32);
            const int rr = (i / 32) % nr;
            const int q  = i % 32;
            *(float4*)(cs + (c * 66 + rr) * 128 + q * 4) =
                *(const float4*)(cb + (size_t)c * (DH * DH) + (r0 + rr) * DH + q * 4);
        }
        __syncthreads();
        for (int idx = tid; idx < 3 * ny * 63; idx += 256) {
            const int c = idx / (ny * 63);
            const int r = idx % (ny * 63);
            const int y = y0 + r / 63;
            const int x = r % 63;
            float s = 0.f;
#pragma unroll
            for (int ci = 0; ci < 3; ci++)
#pragma unroll
                for (int ky = 0; ky < 3; ky++)
#pragma unroll
                    for (int kx = 0; kx < 3; kx++)
                        s += cs[(ci * 66 + (2 * y + ky - r0)) * 128 + 2 * x + kx]
                           * w1s[((c * 3 + ci) * 3 + ky) * 3 + kx];
            s = 0.5f * s * (1.0f + erff(s * 0.70710678118654752f));
            z1[c * 3969 + y * 63 + x] = s;
        }
    }
    __syncthreads();

    __half* fh = gF_h + (size_t)b * FPAD;
    __half* fl = gF_l + (size_t)b * FPAD;
    for (int idx = tid; idx < FLATN; idx += 256) {
        const int c = idx / 961;
        const int r = idx % 961;
        const int y = r / 31, x = r % 31;
        float s = 0.f;
#pragma unroll
        for (int ci = 0; ci < 3; ci++)
#pragma unroll
            for (int ky = 0; ky < 3; ky++)
#pragma unroll
                for (int kx = 0; kx < 3; kx++)
                    s += z1[ci * 3969 + (2 * y + ky) * 63 + (2 * x + kx)]
                       * w2s[((c * 3 + ci) * 3 + ky) * 3 + kx];
        const __half hv = __float2half_rn(s);
        fh[idx] = hv;
        fl[idx] = __float2half_rn(s - __half2float(hv));
    }
    for (int idx = FLATN + tid; idx < FPAD; idx += 256) {
        fh[idx] = __float2half_rn(0.f);
        fl[idx] = __float2half_rn(0.f);
    }
}

// =====================================================================
// K5: classifier head via fp16 mma, 3-pass split, k-split=4 + atomicAdd
// C[256,1000] += 0.5 * [cls|flat] @ [w1;w2]
// grid (m=4, n=8, s=4); CTA tile 64x128; 8 warps 32x32.
// =====================================================================
#define HRSB   80                       // A tile row stride bytes (32k + pad)
#define HBRS   272                      // B tile row stride bytes (128n + pad)
#define OFF_AH2 0
#define OFF_AL2 (64 * HRSB)             // 5120
#define OFF_BH2 (2 * 64 * HRSB)         // 10240
#define OFF_BL2 (OFF_BH2 + 32 * HBRS)   // 18944
#define HSTAGE  (OFF_BL2 + 32 * HBRS)   // 27648
#define HEAD_SMEM (2 * HSTAGE)          // 55296

__device__ __forceinline__ void head_load_stage(
    uint32_t sb, int buf, int chunk, int m0, int n0, int tid)
{
    const uint32_t stg = sb + buf * HSTAGE;
    const bool in_cls = (chunk < HK_CLS_CHUNKS);
    const int  kr     = in_cls ? chunk * 32 : (chunk - HK_CLS_CHUNKS) * 32;
    const __half* Ah = in_cls ? gCls_h : gF_h;
    const __half* Al = in_cls ? gCls_l : gF_l;
    const __half* Bh = in_cls ? gW1_h  : gW2_h;
    const __half* Bl = in_cls ? gW1_l  : gW2_l;
    const int astr = in_cls ? D_ : FPAD;

    // A: 64 rows x 32k -> 256 cp16 slots (hi+lo)
    {
        const int idx = tid;                 // 0..255
        const int row = idx >> 2;
        const int q   = idx & 3;
        const uint32_t doff = (uint32_t)row * HRSB + q * 16;
        const size_t goff = (size_t)(m0 + row) * astr + kr + q * 8;
        cp16(stg + OFF_AH2 + doff, Ah + goff);
        cp16(stg + OFF_AL2 + doff, Al + goff);
    }
    // B: 32 k-rows x 128n -> 512 cp16 slots (hi+lo)
#pragma unroll
    for (int j = 0; j < 2; j++) {
        const int idx = j * 256 + tid;       // 0..511
        const int row = idx >> 4;
        const int q   = idx & 15;
        const uint32_t doff = (uint32_t)row * HBRS + q * 16;
        const size_t goff = (size_t)(kr + row) * NPAD + n0 + q * 8;
        cp16(stg + OFF_BH2 + doff, Bh + goff);
        cp16(stg + OFF_BL2 + doff, Bl + goff);
    }
}

__global__ void __launch_bounds__(256) k_head_mma(float* __restrict__ out)
{
    extern __shared__ char hsm[];
    const uint32_t sb = smem_u32(hsm);
    const int tid  = threadIdx.x;
    const int wid  = tid >> 5;
    const int lane = tid & 31;
    const int wm = wid >> 2;              // 0..1
    const int wn = wid & 3;               // 0..3
    const int m0 = blockIdx.x * 64;
    const int n0 = blockIdx.y * 128;
    const int c0 = blockIdx.z * HK_SPLIT;

    const uint32_t a_row = (lane & 15);
    const uint32_t a_col = (uint32_t)(lane >> 4) * 16;
    const uint32_t br = (lane & 7) + (((lane >> 3) & 1) << 3);
    const uint32_t bc = (uint32_t)(lane >> 4) * 16;

    uint32_t a_off[2], b_off[2];
#pragma unroll
    for (int mt = 0; mt < 2; mt++)
        a_off[mt] = (uint32_t)(wm * 32 + mt * 16 + a_row) * HRSB + a_col;
#pragma unroll
    for (int g = 0; g < 2; g++)
        b_off[g] = br * HBRS + (uint32_t)(wn * 32 + g * 16) * 2 + bc;

    float acc[2][4][4];
#pragma unroll
    for (int mt = 0; mt < 2; mt++)
#pragma unroll
        for (int nf = 0; nf < 4; nf++)
#pragma unroll
            for (int e = 0; e < 4; e++) acc[mt][nf][e] = 0.f;

    head_load_stage(sb, 0, c0, m0, n0, tid);
    CP_COMMIT();

    for (int i = 0; i < HK_SPLIT; i++) {
        if (i + 1 < HK_SPLIT) {
            head_load_stage(sb, (i + 1) & 1, c0 + i + 1, m0, n0, tid);
            CP_COMMIT();
            CP_WAIT1();
        } else {
            CP_WAIT0();
        }
        __syncthreads();

        const uint32_t stg = sb + (i & 1) * HSTAGE;
#pragma unroll
        for (int ks = 0; ks < 2; ks++) {
            uint32_t ah[2][4], al[2][4];
#pragma unroll
            for (int mt = 0; mt < 2; mt++) {
                ldx4(ah[mt], stg + OFF_AH2 + a_off[mt] + ks * 32);
                ldx4(al[mt], stg + OFF_AL2 + a_off[mt] + ks * 32);
            }
            const uint32_t kbb = (uint32_t)ks * 16 * HBRS;
#pragma unroll
            for (int g = 0; g < 2; g++) {
                uint32_t bh[4], bl[4];
                ldx4t(bh, stg + OFF_BH2 + b_off[g] + kbb);
                ldx4t(bl, stg + OFF_BL2 + b_off[g] + kbb);
#pragma unroll
                for (int mt = 0; mt < 2; mt++) {
                    mma16816(acc[mt][2 * g],     ah[mt], bh[0], bh[1]);
                    mma16816(acc[mt][2 * g],     ah[mt], bl[0], bl[1]);
                    mma16816(acc[mt][2 * g],     al[mt], bh[0], bh[1]);
                    mma16816(acc[mt][2 * g + 1], ah[mt], bh[2], bh[3]);
                    mma16816(acc[mt][2 * g + 1], ah[mt], bl[2], bl[3]);
                    mma16816(acc[mt][2 * g + 1], al[mt], bh[2], bh[3]);
                }
            }
        }
        __syncthreads();
    }

    const int gid = lane >> 2;
    const int tig = lane & 3;
#pragma unroll
    for (int mt = 0; mt < 2; mt++) {
        const int r0 = m0 + wm * 32 + mt * 16 + gid;
#pragma unroll
        for (int nf = 0; nf < 4; nf++) {
            const int col = n0 + wn * 32 + nf * 8 + 2 * tig;
            if (col < NC) {
                atomicAdd(out + (size_t)r0 * NC + col,       0.5f * acc[mt][nf][0]);
                atomicAdd(out + (size_t)r0 * NC + col + 1,   0.5f * acc[mt][nf][1]);
                atomicAdd(out + (size_t)(r0 + 8) * NC + col,     0.5f * acc[mt][nf][2]);
                atomicAdd(out + (size_t)(r0 + 8) * NC + col + 1, 0.5f * acc[mt][nf][3]);
            }
        }
    }
}

// =====================================================================
// launch
// =====================================================================
extern "C" void kernel_launch(void* const* d_in, const int* in_sizes, int n_in,
                              void* d_out, int out_size)
{
    const float* cls_token = (const float*)d_in[0];
    const float* x         = (const float*)d_in[1];
    const float* proj_w    = (const float*)d_in[2];
    const float* proj_b    = (const float*)d_in[3];
    const float* ln_g      = (const float*)d_in[4];
    const float* ln_b      = (const float*)d_in[5];
    const float* conv1_w   = (const float*)d_in[6];
    const float* conv2_w   = (const float*)d_in[7];
    const float* cls1_w    = (const float*)d_in[8];
    const float* cls1_b    = (const float*)d_in[9];
    const float* cls2_w    = (const float*)d_in[10];
    const float* cls2_b    = (const float*)d_in[11];
    float* out = (float*)d_out;

    cudaFuncSetAttribute(k_gemm_mma,
                         cudaFuncAttributeMaxDynamicSharedMemorySize, GEMM_SMEM);
    cudaFuncSetAttribute(k_cov_mma,
                         cudaFuncAttributeMaxDynamicSharedMemorySize, COV_SMEM);
    cudaFuncSetAttribute(k_conv,
                         cudaFuncAttributeMaxDynamicSharedMemorySize, CONV_SMEM);
    cudaFuncSetAttribute(k_head_mma,
                         cudaFuncAttributeMaxDynamicSharedMemorySize, HEAD_SMEM);

    k_convA<<<2048, 256>>>(x);                                      // 0
    k_convW<<<dim3(HD / 32, D_ / 32), 256>>>(proj_w);               // 1
    k_convH<<<2048, 256>>>(cls1_w, cls2_w, cls_token,
                           cls1_b, cls2_b, out);                    // 2
    k_gemm_mma<<<dim3(392, 4), 256, GEMM_SMEM>>>(proj_b);           // 3 <- ncu probe
    k_lnc<<<NH * B_, 256>>>(ln_g, ln_b);                            // 4
    k_cov_mma<<<dim3(3, B_), 256, COV_SMEM>>>();                    // 5
    k_conv<<<B_, 256, CONV_SMEM>>>(conv1_w, conv2_w);               // 6
    k_head_mma<<<dim3(4, 8, 4), 256, HEAD_SMEM>>>(out);             // 7
}

// round 11
// speedup vs baseline: 2.9507x; 1.3892x over previous
#include <cuda_runtime.h>
#include <cuda_bf16.h>
#include <cuda_fp16.h>
#include <math.h>
#include <stdint.h>

// ---------------- problem constants ----------------
#define B_    256
#define L_    197
#define LP    196
#define D_    768
#define HD    512
#define DH    128
#define NH    4
#define NC    1000
#define FLATN 2883   // 3*31*31
#define FPAD  2944   // flat padded to multiple of 32
#define NPAD  1024   // classifier N padded
#define HK_CLS_CHUNKS  24          // 768/32
#define HK_CHUNKS      116         // 24 + 92
#define HK_SPLIT       29          // chunks per k-split (116/4)

// ---------------- scratch (static __device__, no allocation) ----------------
__device__ float g_xp[(size_t)B_ * LP * HD];          // 50176 x 512
__device__ float g_cov[(size_t)B_ * 3 * DH * DH];     // (b,p,d,e) NCHW

// fp16 buffers for tensor-core projection GEMM (single-pass: hi only)
__device__ __half gA_h[(size_t)B_ * LP * D_];    // [50176,768]
__device__ __half gWt_h[(size_t)HD * D_];        // [512,768]  W^T

// LN output (UNcentered) fp16 hi, natural layout (h,b, l=196, d=128)
__device__ __half gHn_h[(size_t)NH * B_ * LP * DH];
__device__ float gSh[(size_t)NH * B_ * DH];   // sum_l hi(hn)  (per column)
__device__ float gM [(size_t)NH * B_];        // tile mean (exact)

// classifier-head fp16 buffers (3-pass: hi+lo kept for accuracy)
__device__ __half gW1_h[(size_t)D_ * NPAD];      // [768,1024]
__device__ __half gW1_l[(size_t)D_ * NPAD];
__device__ __half gW2_h[(size_t)FPAD * NPAD];    // [2944,1024]
__device__ __half gW2_l[(size_t)FPAD * NPAD];
__device__ __half gCls_h[(size_t)B_ * D_];       // [256,768]
__device__ __half gCls_l[(size_t)B_ * D_];
__device__ __half gF_h[(size_t)B_ * FPAD];       // [256,2944]
__device__ __half gF_l[(size_t)B_ * FPAD];

// ---------------- baseline-PTX helpers ----------------
__device__ __forceinline__ uint32_t smem_u32(const void* p) {
    uint32_t a;
    asm("{ .reg .u64 t; cvta.to.shared.u64 t, %1; cvt.u32.u64 %0, t; }"
        : "=r"(a) : "l"(p));
    return a;
}
__device__ __forceinline__ void cp16(uint32_t dst, const void* src) {
    asm volatile("cp.async.ca.shared.global [%0], [%1], 16;"
                 :: "r"(dst), "l"(src) : "memory");
}
#define CP_COMMIT() asm volatile("cp.async.commit_group;" ::: "memory")
#define CP_WAIT0()  asm volatile("cp.async.wait_group 0;" ::: "memory")
#define CP_WAIT1()  asm volatile("cp.async.wait_group 1;" ::: "memory")

__device__ __forceinline__ void ldx4(uint32_t* r, uint32_t addr) {
    asm volatile("ldmatrix.sync.aligned.m8n8.x4.shared.b16 {%0,%1,%2,%3}, [%4];"
                 : "=r"(r[0]), "=r"(r[1]), "=r"(r[2]), "=r"(r[3]) : "r"(addr));
}
__device__ __forceinline__ void ldx4t(uint32_t* r, uint32_t addr) {
    asm volatile("ldmatrix.sync.aligned.m8n8.x4.trans.shared.b16 {%0,%1,%2,%3}, [%4];"
                 : "=r"(r[0]), "=r"(r[1]), "=r"(r[2]), "=r"(r[3]) : "r"(addr));
}
__device__ __forceinline__ void mma16816(float* c, const uint32_t* a,
                                         uint32_t b0, uint32_t b1) {
    asm volatile(
        "mma.sync.aligned.m16n8k16.row.col.f32.f16.f16.f32 "
        "{%0,%1,%2,%3}, {%4,%5,%6,%7}, {%8,%9}, {%0,%1,%2,%3};"
        : "+f"(c[0]), "+f"(c[1]), "+f"(c[2]), "+f"(c[3])
        : "r"(a[0]), "r"(a[1]), "r"(a[2]), "r"(a[3]), "r"(b0), "r"(b1));
}

// =====================================================================
// K0a: round x[:,1:,:] to fp16  [50176,768]
// =====================================================================
__global__ void __launch_bounds__(256) k_convA(const float* __restrict__ X)
{
    const int total = B_ * LP * (D_ / 4);
    for (int i = blockIdx.x * blockDim.x + threadIdx.x; i < total;
         i += gridDim.x * blockDim.x) {
        const int m  = i / (D_ / 4);
        const int k4 = i - m * (D_ / 4);
        const int b  = m / LP;
        const int l  = m - b * LP + 1;
        float4 v = *(const float4*)(X + ((size_t)(b * L_ + l)) * D_ + k4 * 4);
        __half2 h01, h23;
        h01.x = __float2half_rn(v.x); h01.y = __float2half_rn(v.y);
        h23.x = __float2half_rn(v.z); h23.y = __float2half_rn(v.w);
        ((__half2*)gA_h)[(size_t)i * 2]     = h01;
        ((__half2*)gA_h)[(size_t)i * 2 + 1] = h23;
    }
}

// =====================================================================
// K0b: W [768,512] -> W^T fp16 [512,768] (hi only; single-pass GEMM)
// =====================================================================
__global__ void __launch_bounds__(256) k_convW(const float* __restrict__ W)
{
    __shared__ float t[32][33];
    const int nb = blockIdx.x * 32;
    const int kb = blockIdx.y * 32;
    const int tx = threadIdx.x & 31, ty = threadIdx.x >> 5;
#pragma unroll
    for (int r = 0; r < 32; r += 8)
        t[ty + r][tx] = W[(size_t)(kb + ty + r) * HD + nb + tx];
    __syncthreads();
#pragma unroll
    for (int r = 0; r < 32; r += 8)
        gWt_h[(size_t)(nb + ty + r) * D_ + kb + tx] = __float2half_rn(t[tx][ty + r]);
}

// =====================================================================
// K0c: head-weight conversions + out init
// =====================================================================
#define CH_S1 (D_ * NPAD)
#define CH_S2 ((size_t)FPAD * NPAD)
#define CH_S3 (B_ * D_)
#define CH_S4 (B_ * NC)
#define CH_TOTAL (CH_S1 + CH_S2 + CH_S3 + CH_S4)

__global__ void __launch_bounds__(256) k_convH(
    const float* __restrict__ w1, const float* __restrict__ w2,
    const float* __restrict__ cls, const float* __restrict__ b1,
    const float* __restrict__ b2, float* __restrict__ out)
{
    for (size_t i = (size_t)blockIdx.x * 256 + threadIdx.x; i < CH_TOTAL;
         i += (size_t)gridDim.x * 256) {
        if (i < CH_S1) {
            const int r = (int)(i >> 10), c = (int)(i & 1023);
            float v = (c < NC) ? w1[(size_t)r * NC + c] : 0.f;
            const __half h = __float2half_rn(v);
            gW1_h[i] = h;
            gW1_l[i] = __float2half_rn(v - __half2float(h));
        } else if (i < CH_S1 + CH_S2) {
            const size_t j = i - CH_S1;
            const int r = (int)(j >> 10), c = (int)(j & 1023);
            float v = (r < FLATN && c < NC) ? w2[(size_t)r * NC + c] : 0.f;
            const __half h = __float2half_rn(v);
            gW2_h[j] = h;
            gW2_l[j] = __float2half_rn(v - __half2float(h));
        } else if (i < CH_S1 + CH_S2 + CH_S3) {
            const size_t j = i - CH_S1 - CH_S2;
            float v = cls[j];
            const __half h = __float2half_rn(v);
            gCls_h[j] = h;
            gCls_l[j] = __float2half_rn(v - __half2float(h));
        } else {
            const size_t j = i - CH_S1 - CH_S2 - CH_S3;
            const int n = (int)(j % NC);
            out[j] = 0.5f * (b1[n] + b2[n]);
        }
    }
}

// =====================================================================
// K1: warp-mma fp16 SINGLE-pass GEMM: xp = A_h @ B_h    <- ncu probe
// CTA tile 128x128, BK=32, 8 warps (warp tile 64x32), 2-stage cp.async.
// =====================================================================
#define RSB      80
#define TILE_B   (128 * RSB)
#define OFF_AH   0
#define OFF_BH   (1 * TILE_B)
#define STAGE_B  (2 * TILE_B)          // 20480
#define GEMM_SMEM (2 * STAGE_B)        // 40960
#define NCHUNK   (D_ / 32)             // 24

__device__ __forceinline__ void gemm_load_stage(
    uint32_t sb, int buf, int c, int m0, int n0, int tid)
{
    const int k0 = c * 32;
    const uint32_t stg = sb + buf * STAGE_B;
#pragma unroll
    for (int q = 0; q < 2; q++) {
        const int ch  = q * 256 + tid;
        const int row = ch >> 2;
        const int cc  = ch & 3;
        const uint32_t doff = (uint32_t)row * RSB + cc * 16;
        const size_t ga = (size_t)(m0 + row) * D_ + k0 + cc * 8;
        const size_t gb = (size_t)(n0 + row) * D_ + k0 + cc * 8;
        cp16(stg + OFF_AH + doff, gA_h + ga);
        cp16(stg + OFF_BH + doff, gWt_h + gb);
    }
}

__global__ void __launch_bounds__(256) k_gemm_mma(const float* __restrict__ bias)
{
    extern __shared__ char smem[];
    const uint32_t sb = smem_u32(smem);
    const int tid  = threadIdx.x;
    const int wid  = tid >> 5;
    const int lane = tid & 31;
    const int wm = wid >> 2;              // 0..1 (m 64 each)
    const int wn = wid & 3;               // 0..3 (n 32 each)
    const int m0 = blockIdx.x * 128;
    const int n0 = blockIdx.y * 128;

    const uint32_t a_row = (lane & 15);
    const uint32_t a_col = (uint32_t)(lane >> 4) * 16;
    const uint32_t b_row = (lane & 7) + ((lane >> 4) << 3);
    const uint32_t b_col = (uint32_t)((lane >> 3) & 1) * 16;

    uint32_t a_off[4], b_off[2];
#pragma unroll
    for (int mt = 0; mt < 4; mt++)
        a_off[mt] = (uint32_t)(wm * 64 + mt * 16 + a_row) * RSB + a_col;
#pragma unroll
    for (int g = 0; g < 2; g++)
        b_off[g] = (uint32_t)(wn * 32 + g * 16 + b_row) * RSB + b_col;

    float acc[4][4][4];
#pragma unroll
    for (int mt = 0; mt < 4; mt++)
#pragma unroll
        for (int nf = 0; nf < 4; nf++)
#pragma unroll
            for (int e = 0; e < 4; e++) acc[mt][nf][e] = 0.f;

    gemm_load_stage(sb, 0, 0, m0, n0, tid);
    CP_COMMIT();

    for (int c = 0; c < NCHUNK; c++) {
        if (c + 1 < NCHUNK) {
            gemm_load_stage(sb, (c + 1) & 1, c + 1, m0, n0, tid);
            CP_COMMIT();
            CP_WAIT1();
        } else {
            CP_WAIT0();
        }
        __syncthreads();

        const uint32_t stg = sb + (c & 1) * STAGE_B;
#pragma unroll
        for (int ks = 0; ks < 2; ks++) {
            const uint32_t kb = (uint32_t)ks * 32;
            uint32_t ah[4][4];
#pragma unroll
            for (int mt = 0; mt < 4; mt++)
                ldx4(ah[mt], stg + OFF_AH + a_off[mt] + kb);
#pragma unroll
            for (int g = 0; g < 2; g++) {
                uint32_t bh[4];
                ldx4(bh, stg + OFF_BH + b_off[g] + kb);
#pragma unroll
                for (int mt = 0; mt < 4; mt++)
                    mma16816(acc[mt][2 * g],     ah[mt], bh[0], bh[1]);
#pragma unroll
                for (int mt = 0; mt < 4; mt++)
                    mma16816(acc[mt][2 * g + 1], ah[mt], bh[2], bh[3]);
            }
        }
        __syncthreads();
    }

    const int gid = lane >> 2;
    const int tig = lane & 3;
#pragma unroll
    for (int mt = 0; mt < 4; mt++) {
        const int r0 = m0 + wm * 64 + mt * 16 + gid;
#pragma unroll
        for (int nf = 0; nf < 4; nf++) {
            const int col = n0 + wn * 32 + nf * 8 + 2 * tig;
            const float b0 = bias[col], b1v = bias[col + 1];
            float2 v0 = make_float2(acc[mt][nf][0] + b0, acc[mt][nf][1] + b1v);
            float2 v1 = make_float2(acc[mt][nf][2] + b0, acc[mt][nf][3] + b1v);
            *(float2*)(g_xp + (size_t)r0 * HD + col)       = v0;
            *(float2*)(g_xp + (size_t)(r0 + 8) * HD + col) = v1;
        }
    }
}

// =====================================================================
// K2: streaming LayerNorm -> fp16 hi (no lo plane) + hi column sums +
// exact tile mean (centering folded into cov as rank-1 correction)
// =====================================================================
__global__ void __launch_bounds__(256) k_lnc(
    const float* __restrict__ g, const float* __restrict__ be)
{
    __shared__ float smh[8][128];
    __shared__ float smf[8][128];

    const int h = blockIdx.x >> 8;
    const int b = blockIdx.x & 255;
    const int tid  = threadIdx.x;
    const int warp = tid >> 5;
    const int lane = tid & 31;

    const float4 gv = *(const float4*)(g + lane * 4);
    const float4 bv = *(const float4*)(be + lane * 4);

    __half* dst_h = gHn_h + ((size_t)(h * B_ + b)) * LP * DH;

    float sh0 = 0.f, sh1 = 0.f, sh2 = 0.f, sh3 = 0.f;
    float sf0 = 0.f, sf1 = 0.f, sf2 = 0.f, sf3 = 0.f;

    for (int l = warp; l < LP; l += 8) {
        const float* src = g_xp + ((size_t)(b * LP + l)) * HD + h * DH;
        float4 v = *(const float4*)(src + lane * 4);

        float s = v.x + v.y + v.z + v.w;
#pragma unroll
        for (int o = 16; o; o >>= 1) s += __shfl_xor_sync(0xffffffffu, s, o);
        const float mu = s * (1.0f / 128.0f);

        const float d0 = v.x - mu, d1 = v.y - mu, d2 = v.z - mu, d3 = v.w - mu;
        float sq = d0 * d0 + d1 * d1 + d2 * d2 + d3 * d3;
#pragma unroll
        for (int o = 16; o; o >>= 1) sq += __shfl_xor_sync(0xffffffffu, sq, o);
        const float rstd = rsqrtf(sq * (1.0f / 128.0f) + 1e-5f);

        const float o0 = d0 * rstd * gv.x + bv.x;
        const float o1 = d1 * rstd * gv.y + bv.y;
        const float o2 = d2 * rstd * gv.z + bv.z;
        const float o3 = d3 * rstd * gv.w + bv.w;

        const __half h0 = __float2half_rn(o0);
        const __half h1 = __float2half_rn(o1);
        const __half h2 = __float2half_rn(o2);
        const __half h3 = __float2half_rn(o3);
        __half2 hh01; hh01.x = h0; hh01.y = h1;
        __half2 hh23; hh23.x = h2; hh23.y = h3;

        const size_t ro = (size_t)l * DH + lane * 4;
        *(__half2*)(dst_h + ro)     = hh01;
        *(__half2*)(dst_h + ro + 2) = hh23;

        sh0 += __half2float(h0); sh1 += __half2float(h1);
        sh2 += __half2float(h2); sh3 += __half2float(h3);
        sf0 += o0; sf1 += o1; sf2 += o2; sf3 += o3;
    }
    smh[warp][lane * 4 + 0] = sh0; smh[warp][lane * 4 + 1] = sh1;
    smh[warp][lane * 4 + 2] = sh2; smh[warp][lane * 4 + 3] = sh3;
    smf[warp][lane * 4 + 0] = sf0; smf[warp][lane * 4 + 1] = sf1;
    smf[warp][lane * 4 + 2] = sf2; smf[warp][lane * 4 + 3] = sf3;
    __syncthreads();

    if (tid < 128) {
        float th = 0.f, tf = 0.f;
#pragma unroll
        for (int w = 0; w < 8; w++) { th += smh[w][tid]; tf += smf[w][tid]; }
        gSh[(size_t)(h * B_ + b) * DH + tid] = th;
        smf[0][tid] = tf;
    }
    __syncthreads();
    if (tid < 32) {
        float t = smf[0][tid] + smf[0][tid + 32] + smf[0][tid + 64] + smf[0][tid + 96];
#pragma unroll
        for (int o = 16; o; o >>= 1) t += __shfl_xor_sync(0xffffffffu, t, o);
        if (tid == 0) gM[h * B_ + b] = t * (1.0f / (LP * DH));
    }
}

// =====================================================================
// K3: cov via fp16 mma SINGLE-pass, trans-ldmatrix, rank-1 centering
// cov = sum x1h x2h - m1*s2h[e] - m2*s1h[d] + Lp*m1*m2, then L2 norm.
// =====================================================================
#define CRS2   136
#define CRSB2  (CRS2 * 2)               // 272 B
#define CTILE2 (208 * CRSB2)            // 56576
#define COV_SMEM (2 * CTILE2)           // 113,152 (2 CTAs/SM possible)

__global__ void __launch_bounds__(256) k_cov_mma()
{
    extern __shared__ char csm[];
    const uint32_t sb = smem_u32(csm);
    __shared__ float colsq[DH];
    __shared__ float s1s[DH];
    __shared__ float s2s[DH];

    const int p = blockIdx.x;
    const int b = blockIdx.y;
    const int tid  = threadIdx.x;
    const int wid  = tid >> 5;
    const int lane = tid & 31;
    const int wm = wid >> 1;
    const int wn = wid & 1;

    const __half* Asrc = gHn_h + ((size_t)(p * B_ + b)) * LP * DH;
    const __half* Bhs  = gHn_h + ((size_t)((p + 1) * B_ + b)) * LP * DH;

    const uint32_t tA = sb, tBh = sb + CTILE2;

    for (int i = tid; i < 2 * 12 * 17; i += 256) {
        const int tile = i / 204;
        const int rem  = i % 204;
        const int r    = rem / 17;
        const int c    = rem % 17;
        *(uint4*)(csm + (size_t)tile * CTILE2 + (196 + r) * CRSB2 + c * 16) =
            make_uint4(0u, 0u, 0u, 0u);
    }
    for (int t = tid; t < LP * 16; t += 256) {
        const int row = t >> 4;
        const int ch  = t & 15;
        const uint32_t doff = (uint32_t)row * CRSB2 + ch * 16;
        const size_t   goff = (size_t)row * DH + ch * 8;
        cp16(tA  + doff, Asrc + goff);
        cp16(tBh + doff, Bhs + goff);
    }
    CP_COMMIT();
    if (tid < DH) {
        colsq[tid] = 0.f;
        s1s[tid] = gSh[(size_t)(p * B_ + b) * DH + tid];
        s2s[tid] = gSh[(size_t)((p + 1) * B_ + b) * DH + tid];
    }
    CP_WAIT0();
    __syncthreads();

    const uint32_t ar = (lane & 7) + ((lane >> 4) << 3);
    const uint32_t ac = ((lane >> 3) & 1) * 16;
    const uint32_t br = (lane & 7) + (((lane >> 3) & 1) << 3);
    const uint32_t bc = (uint32_t)(lane >> 4) * 16;

    uint32_t a_off[2], b_off[4];
#pragma unroll
    for (int mt = 0; mt < 2; mt++)
        a_off[mt] = ar * CRSB2 + (uint32_t)(wm * 32 + mt * 16) * 2 + ac;
#pragma unroll
    for (int g = 0; g < 4; g++)
        b_off[g] = br * CRSB2 + (uint32_t)(wn * 64 + g * 16) * 2 + bc;

    float acc[2][8][4];
#pragma unroll
    for (int mt = 0; mt < 2; mt++)
#pragma unroll
        for (int nt = 0; nt < 8; nt++)
#pragma unroll
            for (int e = 0; e < 4; e++) acc[mt][nt][e] = 0.f;

#pragma unroll
    for (int ks = 0; ks < 13; ks++) {
        const uint32_t kb = (uint32_t)ks * 16 * CRSB2;
        uint32_t ah[2][4];
#pragma unroll
        for (int mt = 0; mt < 2; mt++)
            ldx4t(ah[mt], tA + a_off[mt] + kb);
#pragma unroll
        for (int g = 0; g < 4; g++) {
            uint32_t bh[4];
            ldx4t(bh, tBh + b_off[g] + kb);
#pragma unroll
            for (int mt = 0; mt < 2; mt++) {
                mma16816(acc[mt][2 * g],     ah[mt], bh[0], bh[1]);
                mma16816(acc[mt][2 * g + 1], ah[mt], bh[2], bh[3]);
            }
        }
    }

    const float m1 = gM[p * B_ + b];
    const float m2 = gM[(p + 1) * B_ + b];
    const float c12 = (float)LP * m1 * m2;
    const int gid = lane >> 2;
    const int tig = lane & 3;
#pragma unroll
    for (int mt = 0; mt < 2; mt++) {
        const int d0 = wm * 32 + mt * 16 + gid;
        const float t1a = m2 * s1s[d0]     - c12;
        const float t1b = m2 * s1s[d0 + 8] - c12;
#pragma unroll
        for (int nt = 0; nt < 8; nt++) {
            const int e0 = wn * 64 + nt * 8 + 2 * tig;
            const float t2a = m1 * s2s[e0];
            const float t2b = m1 * s2s[e0 + 1];
            acc[mt][nt][0] -= t1a + t2a;
            acc[mt][nt][1] -= t1a + t2b;
            acc[mt][nt][2] -= t1b + t2a;
            acc[mt][nt][3] -= t1b + t2b;
        }
    }

#pragma unroll
    for (int nt = 0; nt < 8; nt++) {
        float s0 = acc[0][nt][0] * acc[0][nt][0] + acc[0][nt][2] * acc[0][nt][2]
                 + acc[1][nt][0] * acc[1][nt][0] + acc[1][nt][2] * acc[1][nt][2];
        float s1 = acc[0][nt][1] * acc[0][nt][1] + acc[0][nt][3] * acc[0][nt][3]
                 + acc[1][nt][1] * acc[1][nt][1] + acc[1][nt][3] * acc[1][nt][3];
#pragma unroll
        for (int o = 4; o <= 16; o <<= 1) {
            s0 += __shfl_xor_sync(0xffffffffu, s0, o);
            s1 += __shfl_xor_sync(0xffffffffu, s1, o);
        }
        if (lane < 4) {
            const int col = wn * 64 + nt * 8 + 2 * lane;
            atomicAdd(&colsq[col], s0);
            atomicAdd(&colsq[col + 1], s1);
        }
    }
    __syncthreads();

    float* outb = g_cov + ((size_t)(b * 3 + p)) * (DH * DH);
#pragma unroll
    for (int nt = 0; nt < 8; nt++) {
        const int col = wn * 64 + nt * 8 + 2 * tig;
        const float i0 = 1.0f / fmaxf(sqrtf(colsq[col]),     (float)LP * 1e-12f);
        const float i1 = 1.0f / fmaxf(sqrtf(colsq[col + 1]), (float)LP * 1e-12f);
#pragma unroll
        for (int mt = 0; mt < 2; mt++) {
            const int r0 = wm * 32 + mt * 16 + gid;
            float2 v0 = make_float2(acc[mt][nt][0] * i0, acc[mt][nt][1] * i1);
            float2 v1 = make_float2(acc[mt][nt][2] * i0, acc[mt][nt][3] * i1);
            *(float2*)(outb + (size_t)r0 * DH + col)       = v0;
            *(float2*)(outb + (size_t)(r0 + 8) * DH + col) = v1;
        }
    }
}

// =====================================================================
// K4: fused conv1 -> GELU -> conv2 ; emits flat as fp16 hi/lo (padded)
// =====================================================================
#define CONV_CS_B  (3 * 66 * 128 * 4)
#define CONV_SMEM  (CONV_CS_B + 3 * 3969 * 4)  // 149,004

__global__ void __launch_bounds__(256) k_conv(
    const float* __restrict__ w1, const float* __restrict__ w2)
{
    extern __shared__ char cvsm[];
    float* cs = (float*)cvsm;
    float* z1 = (float*)(cvsm + CONV_CS_B);
    __shared__ float w1s[81];
    __shared__ float w2s[81];

    const int b = blockIdx.x;
    const int tid = threadIdx.x;
    if (tid < 81) { w1s[tid] = w1[tid]; w2s[tid] = w2[tid]; }

    const float* cb = g_cov + (size_t)b * 3 * DH * DH;

#pragma unroll 1
    for (int ph = 0; ph < 2; ph++) {
        const int r0 = ph * 64;
        const int nr = ph ? 64 : 66;
        const int y0 = ph ? 32 : 0;
        const int ny = ph ? 31 : 32;
        __syncthreads();
        for (int i = tid; i < 3 * nr * 32; i += 256) {
            const int c  = i / (nr * 32);
            const int rr = (i / 32) % nr;
            const int q  = i % 32;
            *(float4*)(cs + (c * 66 + rr) * 128 + q * 4) =
                *(const float4*)(cb + (size_t)c * (DH * DH) + (r0 + rr) * DH + q * 4);
        }
        __syncthreads();
        for (int idx = tid; idx < 3 * ny * 63; idx += 256) {
            const int c = idx / (ny * 63);
            const int r = idx % (ny * 63);
            const int y = y0 + r / 63;
            const int x = r % 63;
            float s = 0.f;
#pragma unroll
            for (int ci = 0; ci < 3; ci++)
#pragma unroll
                for (int ky = 0; ky < 3; ky++)
#pragma unroll
                    for (int kx = 0; kx < 3; kx++)
                        s += cs[(ci * 66 + (2 * y + ky - r0)) * 128 + 2 * x + kx]
                           * w1s[((c * 3 + ci) * 3 + ky) * 3 + kx];
            s = 0.5f * s * (1.0f + erff(s * 0.70710678118654752f));
            z1[c * 3969 + y * 63 + x] = s;
        }
    }
    __syncthreads();

    __half* fh = gF_h + (size_t)b * FPAD;
    __half* fl = gF_l + (size_t)b * FPAD;
    for (int idx = tid; idx < FLATN; idx += 256) {
        const int c = idx / 961;
        const int r = idx % 961;
        const int y = r / 31, x = r % 31;
        float s = 0.f;
#pragma unroll
        for (int ci = 0; ci < 3; ci++)
#pragma unroll
            for (int ky = 0; ky < 3; ky++)
#pragma unroll
                for (int kx = 0; kx < 3; kx++)
                    s += z1[ci * 3969 + (2 * y + ky) * 63 + (2 * x + kx)]
                       * w2s[((c * 3 + ci) * 3 + ky) * 3 + kx];
        const __half hv = __float2half_rn(s);
        fh[idx] = hv;
        fl[idx] = __float2half_rn(s - __half2float(hv));
    }
    for (int idx = FLATN + tid; idx < FPAD; idx += 256) {
        fh[idx] = __float2half_rn(0.f);
        fl[idx] = __float2half_rn(0.f);
    }
}

// =====================================================================
// K5: classifier head via fp16 mma, 3-pass split, k-split=4 + atomicAdd
// =====================================================================
#define HRSB   80
#define HBRS   272
#define OFF_AH2 0
#define OFF_AL2 (64 * HRSB)
#define OFF_BH2 (2 * 64 * HRSB)
#define OFF_BL2 (OFF_BH2 + 32 * HBRS)
#define HSTAGE  (OFF_BL2 + 32 * HBRS)   // 27648
#define HEAD_SMEM (2 * HSTAGE)          // 55296

__device__ __forceinline__ void head_load_stage(
    uint32_t sb, int buf, int chunk, int m0, int n0, int tid)
{
    const uint32_t stg = sb + buf * HSTAGE;
    const bool in_cls = (chunk < HK_CLS_CHUNKS);
    const int  kr     = in_cls ? chunk * 32 : (chunk - HK_CLS_CHUNKS) * 32;
    const __half* Ah = in_cls ? gCls_h : gF_h;
    const __half* Al = in_cls ? gCls_l : gF_l;
    const __half* Bh = in_cls ? gW1_h  : gW2_h;
    const __half* Bl = in_cls ? gW1_l  : gW2_l;
    const int astr = in_cls ? D_ : FPAD;

    {
        const int idx = tid;
        const int row = idx >> 2;
        const int q   = idx & 3;
        const uint32_t doff = (uint32_t)row * HRSB + q * 16;
        const size_t goff = (size_t)(m0 + row) * astr + kr + q * 8;
        cp16(stg + OFF_AH2 + doff, Ah + goff);
        cp16(stg + OFF_AL2 + doff, Al + goff);
    }
#pragma unroll
    for (int j = 0; j < 2; j++) {
        const int idx = j * 256 + tid;
        const int row = idx >> 4;
        const int q   = idx & 15;
        const uint32_t doff = (uint32_t)row * HBRS + q * 16;
        const size_t goff = (size_t)(kr + row) * NPAD + n0 + q * 8;
        cp16(stg + OFF_BH2 + doff, Bh + goff);
        cp16(stg + OFF_BL2 + doff, Bl + goff);
    }
}

__global__ void __launch_bounds__(256) k_head_mma(float* __restrict__ out)
{
    extern __shared__ char hsm[];
    const uint32_t sb = smem_u32(hsm);
    const int tid  = threadIdx.x;
    const int wid  = tid >> 5;
    const int lane = tid & 31;
    const int wm = wid >> 2;
    const int wn = wid & 3;
    const int m0 = blockIdx.x * 64;
    const int n0 = blockIdx.y * 128;
    const int c0 = blockIdx.z * HK_SPLIT;

    const uint32_t a_row = (lane & 15);
    const uint32_t a_col = (uint32_t)(lane >> 4) * 16;
    const uint32_t br = (lane & 7) + (((lane >> 3) & 1) << 3);
    const uint32_t bc = (uint32_t)(lane >> 4) * 16;

    uint32_t a_off[2], b_off[2];
#pragma unroll
    for (int mt = 0; mt < 2; mt++)
        a_off[mt] = (uint32_t)(wm * 32 + mt * 16 + a_row) * HRSB + a_col;
#pragma unroll
    for (int g = 0; g < 2; g++)
        b_off[g] = br * HBRS + (uint32_t)(wn * 32 + g * 16) * 2 + bc;

    float acc[2][4][4];
#pragma unroll
    for (int mt = 0; mt < 2; mt++)
#pragma unroll
        for (int nf = 0; nf < 4; nf++)
#pragma unroll
            for (int e = 0; e < 4; e++) acc[mt][nf][e] = 0.f;

    head_load_stage(sb, 0, c0, m0, n0, tid);
    CP_COMMIT();

    for (int i = 0; i < HK_SPLIT; i++) {
        if (i + 1 < HK_SPLIT) {
            head_load_stage(sb, (i + 1) & 1, c0 + i + 1, m0, n0, tid);
            CP_COMMIT();
            CP_WAIT1();
        } else {
            CP_WAIT0();
        }
        __syncthreads();

        const uint32_t stg = sb + (i & 1) * HSTAGE;
#pragma unroll
        for (int ks = 0; ks < 2; ks++) {
            uint32_t ah[2][4], al[2][4];
#pragma unroll
            for (int mt = 0; mt < 2; mt++) {
                ldx4(ah[mt], stg + OFF_AH2 + a_off[mt] + ks * 32);
                ldx4(al[mt], stg + OFF_AL2 + a_off[mt] + ks * 32);
            }
            const uint32_t kbb = (uint32_t)ks * 16 * HBRS;
#pragma unroll
            for (int g = 0; g < 2; g++) {
                uint32_t bh[4], bl[4];
                ldx4t(bh, stg + OFF_BH2 + b_off[g] + kbb);
                ldx4t(bl, stg + OFF_BL2 + b_off[g] + kbb);
#pragma unroll
                for (int mt = 0; mt < 2; mt++) {
                    mma16816(acc[mt][2 * g],     ah[mt], bh[0], bh[1]);
                    mma16816(acc[mt][2 * g],     ah[mt], bl[0], bl[1]);
                    mma16816(acc[mt][2 * g],     al[mt], bh[0], bh[1]);
                    mma16816(acc[mt][2 * g + 1], ah[mt], bh[2], bh[3]);
                    mma16816(acc[mt][2 * g + 1], ah[mt], bl[2], bl[3]);
                    mma16816(acc[mt][2 * g + 1], al[mt], bh[2], bh[3]);
                }
            }
        }
        __syncthreads();
    }

    const int gid = lane >> 2;
    const int tig = lane & 3;
#pragma unroll
    for (int mt = 0; mt < 2; mt++) {
        const int r0 = m0 + wm * 32 + mt * 16 + gid;
#pragma unroll
        for (int nf = 0; nf < 4; nf++) {
            const int col = n0 + wn * 32 + nf * 8 + 2 * tig;
            if (col < NC) {
                atomicAdd(out + (size_t)r0 * NC + col,       0.5f * acc[mt][nf][0]);
                atomicAdd(out + (size_t)r0 * NC + col + 1,   0.5f * acc[mt][nf][1]);
                atomicAdd(out + (size_t)(r0 + 8) * NC + col,     0.5f * acc[mt][nf][2]);
                atomicAdd(out + (size_t)(r0 + 8) * NC + col + 1, 0.5f * acc[mt][nf][3]);
            }
        }
    }
}

// =====================================================================
// launch
// =====================================================================
extern "C" void kernel_launch(void* const* d_in, const int* in_sizes, int n_in,
                              void* d_out, int out_size)
{
    const float* cls_token = (const float*)d_in[0];
    const float* x         = (const float*)d_in[1];
    const float* proj_w    = (const float*)d_in[2];
    const float* proj_b    = (const float*)d_in[3];
    const float* ln_g      = (const float*)d_in[4];
    const float* ln_b      = (const float*)d_in[5];
    const float* conv1_w   = (const float*)d_in[6];
    const float* conv2_w   = (const float*)d_in[7];
    const float* cls1_w    = (const float*)d_in[8];
    const float* cls1_b    = (const float*)d_in[9];
    const float* cls2_w    = (const float*)d_in[10];
    const float* cls2_b    = (const float*)d_in[11];
    float* out = (float*)d_out;

    cudaFuncSetAttribute(k_gemm_mma,
                         cudaFuncAttributeMaxDynamicSharedMemorySize, GEMM_SMEM);
    cudaFuncSetAttribute(k_cov_mma,
                         cudaFuncAttributeMaxDynamicSharedMemorySize, COV_SMEM);
    cudaFuncSetAttribute(k_conv,
                         cudaFuncAttributeMaxDynamicSharedMemorySize, CONV_SMEM);
    cudaFuncSetAttribute(k_head_mma,
                         cudaFuncAttributeMaxDynamicSharedMemorySize, HEAD_SMEM);

    k_convA<<<2048, 256>>>(x);                                      // 0
    k_convW<<<dim3(HD / 32, D_ / 32), 256>>>(proj_w);               // 1
    k_convH<<<2048, 256>>>(cls1_w, cls2_w, cls_token,
                           cls1_b, cls2_b, out);                    // 2
    k_gemm_mma<<<dim3(392, 4), 256, GEMM_SMEM>>>(proj_b);           // 3 <- ncu probe
    k_lnc<<<NH * B_, 256>>>(ln_g, ln_b);                            // 4
    k_cov_mma<<<dim3(3, B_), 256, COV_SMEM>>>();                    // 5
    k_conv<<<B_, 256, CONV_SMEM>>>(conv1_w, conv2_w);               // 6
    k_head_mma<<<dim3(4, 8, 4), 256, HEAD_SMEM>>>(out);             // 7
}

// round 12
// speedup vs baseline: 3.0357x; 1.0288x over previous
#include <cuda_runtime.h>
#include <cuda_bf16.h>
#include <cuda_fp16.h>
#include <math.h>
#include <stdint.h>

// ---------------- problem constants ----------------
#define B_    256
#define L_    197
#define LP    196
#define D_    768
#define HD    512
#define DH    128
#define NH    4
#define NC    1000
#define FLATN 2883   // 3*31*31
#define FPAD  2944   // flat padded to multiple of 32
#define NPAD  1024   // classifier N padded
#define HK_CLS_CHUNKS  24          // 768/32
#define HK_CHUNKS      116         // 24 + 92
#define HK_SPLIT       29          // chunks per k-split (116/4)

// ---------------- scratch (static __device__, no allocation) ----------------
__device__ float g_xp[(size_t)B_ * LP * HD];          // 50176 x 512
__device__ float g_cov[(size_t)B_ * 3 * DH * DH];     // (b,p,d,e) NCHW

// fp16 buffers for tensor-core projection GEMM (single-pass: hi only)
__device__ __half gA_h[(size_t)B_ * LP * D_];    // [50176,768]
__device__ __half gWt_h[(size_t)HD * D_];        // [512,768]  W^T

// LN output (UNcentered) fp16 hi, natural layout (h,b, l=196, d=128)
__device__ __half gHn_h[(size_t)NH * B_ * LP * DH];
__device__ float gSh[(size_t)NH * B_ * DH];   // sum_l hi(hn)  (per column)
__device__ float gM [(size_t)NH * B_];        // tile mean (exact)

// classifier-head fp16 buffers (3-pass: hi+lo kept for accuracy)
__device__ __half gW1_h[(size_t)D_ * NPAD];      // [768,1024]
__device__ __half gW1_l[(size_t)D_ * NPAD];
__device__ __half gW2_h[(size_t)FPAD * NPAD];    // [2944,1024]
__device__ __half gW2_l[(size_t)FPAD * NPAD];
__device__ __half gCls_h[(size_t)B_ * D_];       // [256,768]
__device__ __half gCls_l[(size_t)B_ * D_];
__device__ __half gF_h[(size_t)B_ * FPAD];       // [256,2944]
__device__ __half gF_l[(size_t)B_ * FPAD];

// ---------------- baseline-PTX helpers ----------------
__device__ __forceinline__ uint32_t smem_u32(const void* p) {
    uint32_t a;
    asm("{ .reg .u64 t; cvta.to.shared.u64 t, %1; cvt.u32.u64 %0, t; }"
        : "=r"(a) : "l"(p));
    return a;
}
__device__ __forceinline__ void cp16(uint32_t dst, const void* src) {
    asm volatile("cp.async.ca.shared.global [%0], [%1], 16;"
                 :: "r"(dst), "l"(src) : "memory");
}
#define CP_COMMIT() asm volatile("cp.async.commit_group;" ::: "memory")
#define CP_WAIT0()  asm volatile("cp.async.wait_group 0;" ::: "memory")
#define CP_WAIT1()  asm volatile("cp.async.wait_group 1;" ::: "memory")

__device__ __forceinline__ void ldx4(uint32_t* r, uint32_t addr) {
    asm volatile("ldmatrix.sync.aligned.m8n8.x4.shared.b16 {%0,%1,%2,%3}, [%4];"
                 : "=r"(r[0]), "=r"(r[1]), "=r"(r[2]), "=r"(r[3]) : "r"(addr));
}
__device__ __forceinline__ void ldx4t(uint32_t* r, uint32_t addr) {
    asm volatile("ldmatrix.sync.aligned.m8n8.x4.trans.shared.b16 {%0,%1,%2,%3}, [%4];"
                 : "=r"(r[0]), "=r"(r[1]), "=r"(r[2]), "=r"(r[3]) : "r"(addr));
}
__device__ __forceinline__ void mma16816(float* c, const uint32_t* a,
                                         uint32_t b0, uint32_t b1) {
    asm volatile(
        "mma.sync.aligned.m16n8k16.row.col.f32.f16.f16.f32 "
        "{%0,%1,%2,%3}, {%4,%5,%6,%7}, {%8,%9}, {%0,%1,%2,%3};"
        : "+f"(c[0]), "+f"(c[1]), "+f"(c[2]), "+f"(c[3])
        : "r"(a[0]), "r"(a[1]), "r"(a[2]), "r"(a[3]), "r"(b0), "r"(b1));
}

// =====================================================================
// K0a: round x[:,1:,:] to fp16  [50176,768]
// =====================================================================
__global__ void __launch_bounds__(256) k_convA(const float* __restrict__ X)
{
    const int total = B_ * LP * (D_ / 4);
    for (int i = blockIdx.x * blockDim.x + threadIdx.x; i < total;
         i += gridDim.x * blockDim.x) {
        const int m  = i / (D_ / 4);
        const int k4 = i - m * (D_ / 4);
        const int b  = m / LP;
        const int l  = m - b * LP + 1;
        float4 v = *(const float4*)(X + ((size_t)(b * L_ + l)) * D_ + k4 * 4);
        __half2 h01, h23;
        h01.x = __float2half_rn(v.x); h01.y = __float2half_rn(v.y);
        h23.x = __float2half_rn(v.z); h23.y = __float2half_rn(v.w);
        ((__half2*)gA_h)[(size_t)i * 2]     = h01;
        ((__half2*)gA_h)[(size_t)i * 2 + 1] = h23;
    }
}

// =====================================================================
// K0b: W [768,512] -> W^T fp16 [512,768] (hi only; single-pass GEMM)
// =====================================================================
__global__ void __launch_bounds__(256) k_convW(const float* __restrict__ W)
{
    __shared__ float t[32][33];
    const int nb = blockIdx.x * 32;
    const int kb = blockIdx.y * 32;
    const int tx = threadIdx.x & 31, ty = threadIdx.x >> 5;
#pragma unroll
    for (int r = 0; r < 32; r += 8)
        t[ty + r][tx] = W[(size_t)(kb + ty + r) * HD + nb + tx];
    __syncthreads();
#pragma unroll
    for (int r = 0; r < 32; r += 8)
        gWt_h[(size_t)(nb + ty + r) * D_ + kb + tx] = __float2half_rn(t[tx][ty + r]);
}

// =====================================================================
// K0c: head-weight conversions + out init
// =====================================================================
#define CH_S1 (D_ * NPAD)
#define CH_S2 ((size_t)FPAD * NPAD)
#define CH_S3 (B_ * D_)
#define CH_S4 (B_ * NC)
#define CH_TOTAL (CH_S1 + CH_S2 + CH_S3 + CH_S4)

__global__ void __launch_bounds__(256) k_convH(
    const float* __restrict__ w1, const float* __restrict__ w2,
    const float* __restrict__ cls, const float* __restrict__ b1,
    const float* __restrict__ b2, float* __restrict__ out)
{
    for (size_t i = (size_t)blockIdx.x * 256 + threadIdx.x; i < CH_TOTAL;
         i += (size_t)gridDim.x * 256) {
        if (i < CH_S1) {
            const int r = (int)(i >> 10), c = (int)(i & 1023);
            float v = (c < NC) ? w1[(size_t)r * NC + c] : 0.f;
            const __half h = __float2half_rn(v);
            gW1_h[i] = h;
            gW1_l[i] = __float2half_rn(v - __half2float(h));
        } else if (i < CH_S1 + CH_S2) {
            const size_t j = i - CH_S1;
            const int r = (int)(j >> 10), c = (int)(j & 1023);
            float v = (r < FLATN && c < NC) ? w2[(size_t)r * NC + c] : 0.f;
            const __half h = __float2half_rn(v);
            gW2_h[j] = h;
            gW2_l[j] = __float2half_rn(v - __half2float(h));
        } else if (i < CH_S1 + CH_S2 + CH_S3) {
            const size_t j = i - CH_S1 - CH_S2;
            float v = cls[j];
            const __half h = __float2half_rn(v);
            gCls_h[j] = h;
            gCls_l[j] = __float2half_rn(v - __half2float(h));
        } else {
            const size_t j = i - CH_S1 - CH_S2 - CH_S3;
            const int n = (int)(j % NC);
            out[j] = 0.5f * (b1[n] + b2[n]);
        }
    }
}

// =====================================================================
// K1: warp-mma fp16 single-pass GEMM: xp = A_h @ B_h    <- ncu probe
// CTA tile 128x128, BK=32, 4 warps (block=128), warp tile 64x64:
// 8 ldx4 -> 32 mma per warp-ks (1.0 smem wavefront per mma; was 1.5).
// 2-stage cp.async pipeline.
// =====================================================================
#define RSB      80
#define TILE_B   (128 * RSB)
#define OFF_AH   0
#define OFF_BH   (1 * TILE_B)
#define STAGE_B  (2 * TILE_B)          // 20480
#define GEMM_SMEM (2 * STAGE_B)        // 40960
#define NCHUNK   (D_ / 32)             // 24

__device__ __forceinline__ void gemm_load_stage(
    uint32_t sb, int buf, int c, int m0, int n0, int tid)
{
    const int k0 = c * 32;
    const uint32_t stg = sb + buf * STAGE_B;
#pragma unroll
    for (int q = 0; q < 4; q++) {
        const int ch  = q * 128 + tid;      // 0..511 (16B units per tile)
        const int row = ch >> 2;
        const int cc  = ch & 3;
        const uint32_t doff = (uint32_t)row * RSB + cc * 16;
        const size_t ga = (size_t)(m0 + row) * D_ + k0 + cc * 8;
        const size_t gb = (size_t)(n0 + row) * D_ + k0 + cc * 8;
        cp16(stg + OFF_AH + doff, gA_h + ga);
        cp16(stg + OFF_BH + doff, gWt_h + gb);
    }
}

__global__ void __launch_bounds__(128) k_gemm_mma(const float* __restrict__ bias)
{
    extern __shared__ char smem[];
    const uint32_t sb = smem_u32(smem);
    const int tid  = threadIdx.x;
    const int wid  = tid >> 5;
    const int lane = tid & 31;
    const int wm = wid >> 1;              // 0..1 (m 64 each)
    const int wn = wid & 1;               // 0..1 (n 64 each)
    const int m0 = blockIdx.x * 128;
    const int n0 = blockIdx.y * 128;

    const uint32_t a_row = (lane & 15);
    const uint32_t a_col = (uint32_t)(lane >> 4) * 16;
    const uint32_t b_row = (lane & 7) + ((lane >> 4) << 3);
    const uint32_t b_col = (uint32_t)((lane >> 3) & 1) * 16;

    uint32_t a_off[4], b_off[4];
#pragma unroll
    for (int mt = 0; mt < 4; mt++)
        a_off[mt] = (uint32_t)(wm * 64 + mt * 16 + a_row) * RSB + a_col;
#pragma unroll
    for (int g = 0; g < 4; g++)
        b_off[g] = (uint32_t)(wn * 64 + g * 16 + b_row) * RSB + b_col;

    // acc[mt][nt][4] with nt = g*2 + n8half  (8 n8-blocks across 64 n)
    float acc[4][8][4];
#pragma unroll
    for (int mt = 0; mt < 4; mt++)
#pragma unroll
        for (int nt = 0; nt < 8; nt++)
#pragma unroll
            for (int e = 0; e < 4; e++) acc[mt][nt][e] = 0.f;

    gemm_load_stage(sb, 0, 0, m0, n0, tid);
    CP_COMMIT();

    for (int c = 0; c < NCHUNK; c++) {
        if (c + 1 < NCHUNK) {
            gemm_load_stage(sb, (c + 1) & 1, c + 1, m0, n0, tid);
            CP_COMMIT();
            CP_WAIT1();
        } else {
            CP_WAIT0();
        }
        __syncthreads();

        const uint32_t stg = sb + (c & 1) * STAGE_B;
#pragma unroll
        for (int ks = 0; ks < 2; ks++) {
            const uint32_t kb = (uint32_t)ks * 32;
            uint32_t ah[4][4];
#pragma unroll
            for (int mt = 0; mt < 4; mt++)
                ldx4(ah[mt], stg + OFF_AH + a_off[mt] + kb);
#pragma unroll
            for (int g = 0; g < 4; g++) {
                uint32_t bh[4];
                ldx4(bh, stg + OFF_BH + b_off[g] + kb);
#pragma unroll
                for (int mt = 0; mt < 4; mt++)
                    mma16816(acc[mt][2 * g],     ah[mt], bh[0], bh[1]);
#pragma unroll
                for (int mt = 0; mt < 4; mt++)
                    mma16816(acc[mt][2 * g + 1], ah[mt], bh[2], bh[3]);
            }
        }
        __syncthreads();
    }

    const int gid = lane >> 2;
    const int tig = lane & 3;
#pragma unroll
    for (int mt = 0; mt < 4; mt++) {
        const int r0 = m0 + wm * 64 + mt * 16 + gid;
#pragma unroll
        for (int nt = 0; nt < 8; nt++) {
            const int col = n0 + wn * 64 + nt * 8 + 2 * tig;
            const float b0 = bias[col], b1v = bias[col + 1];
            float2 v0 = make_float2(acc[mt][nt][0] + b0, acc[mt][nt][1] + b1v);
            float2 v1 = make_float2(acc[mt][nt][2] + b0, acc[mt][nt][3] + b1v);
            *(float2*)(g_xp + (size_t)r0 * HD + col)       = v0;
            *(float2*)(g_xp + (size_t)(r0 + 8) * HD + col) = v1;
        }
    }
}

// =====================================================================
// K2: streaming LayerNorm -> fp16 hi + hi column sums + exact tile mean
// =====================================================================
__global__ void __launch_bounds__(256) k_lnc(
    const float* __restrict__ g, const float* __restrict__ be)
{
    __shared__ float smh[8][128];
    __shared__ float smf[8][128];

    const int h = blockIdx.x >> 8;
    const int b = blockIdx.x & 255;
    const int tid  = threadIdx.x;
    const int warp = tid >> 5;
    const int lane = tid & 31;

    const float4 gv = *(const float4*)(g + lane * 4);
    const float4 bv = *(const float4*)(be + lane * 4);

    __half* dst_h = gHn_h + ((size_t)(h * B_ + b)) * LP * DH;

    float sh0 = 0.f, sh1 = 0.f, sh2 = 0.f, sh3 = 0.f;
    float sf0 = 0.f, sf1 = 0.f, sf2 = 0.f, sf3 = 0.f;

    for (int l = warp; l < LP; l += 8) {
        const float* src = g_xp + ((size_t)(b * LP + l)) * HD + h * DH;
        float4 v = *(const float4*)(src + lane * 4);

        float s = v.x + v.y + v.z + v.w;
#pragma unroll
        for (int o = 16; o; o >>= 1) s += __shfl_xor_sync(0xffffffffu, s, o);
        const float mu = s * (1.0f / 128.0f);

        const float d0 = v.x - mu, d1 = v.y - mu, d2 = v.z - mu, d3 = v.w - mu;
        float sq = d0 * d0 + d1 * d1 + d2 * d2 + d3 * d3;
#pragma unroll
        for (int o = 16; o; o >>= 1) sq += __shfl_xor_sync(0xffffffffu, sq, o);
        const float rstd = rsqrtf(sq * (1.0f / 128.0f) + 1e-5f);

        const float o0 = d0 * rstd * gv.x + bv.x;
        const float o1 = d1 * rstd * gv.y + bv.y;
        const float o2 = d2 * rstd * gv.z + bv.z;
        const float o3 = d3 * rstd * gv.w + bv.w;

        const __half h0 = __float2half_rn(o0);
        const __half h1 = __float2half_rn(o1);
        const __half h2 = __float2half_rn(o2);
        const __half h3 = __float2half_rn(o3);
        __half2 hh01; hh01.x = h0; hh01.y = h1;
        __half2 hh23; hh23.x = h2; hh23.y = h3;

        const size_t ro = (size_t)l * DH + lane * 4;
        *(__half2*)(dst_h + ro)     = hh01;
        *(__half2*)(dst_h + ro + 2) = hh23;

        sh0 += __half2float(h0); sh1 += __half2float(h1);
        sh2 += __half2float(h2); sh3 += __half2float(h3);
        sf0 += o0; sf1 += o1; sf2 += o2; sf3 += o3;
    }
    smh[warp][lane * 4 + 0] = sh0; smh[warp][lane * 4 + 1] = sh1;
    smh[warp][lane * 4 + 2] = sh2; smh[warp][lane * 4 + 3] = sh3;
    smf[warp][lane * 4 + 0] = sf0; smf[warp][lane * 4 + 1] = sf1;
    smf[warp][lane * 4 + 2] = sf2; smf[warp][lane * 4 + 3] = sf3;
    __syncthreads();

    if (tid < 128) {
        float th = 0.f, tf = 0.f;
#pragma unroll
        for (int w = 0; w < 8; w++) { th += smh[w][tid]; tf += smf[w][tid]; }
        gSh[(size_t)(h * B_ + b) * DH + tid] = th;
        smf[0][tid] = tf;
    }
    __syncthreads();
    if (tid < 32) {
        float t = smf[0][tid] + smf[0][tid + 32] + smf[0][tid + 64] + smf[0][tid + 96];
#pragma unroll
        for (int o = 16; o; o >>= 1) t += __shfl_xor_sync(0xffffffffu, t, o);
        if (tid == 0) gM[h * B_ + b] = t * (1.0f / (LP * DH));
    }
}

// =====================================================================
// K3: cov via fp16 mma single-pass, trans-ldmatrix, rank-1 centering
// =====================================================================
#define CRS2   136
#define CRSB2  (CRS2 * 2)               // 272 B
#define CTILE2 (208 * CRSB2)            // 56576
#define COV_SMEM (2 * CTILE2)           // 113,152

__global__ void __launch_bounds__(256) k_cov_mma()
{
    extern __shared__ char csm[];
    const uint32_t sb = smem_u32(csm);
    __shared__ float colsq[DH];
    __shared__ float s1s[DH];
    __shared__ float s2s[DH];

    const int p = blockIdx.x;
    const int b = blockIdx.y;
    const int tid  = threadIdx.x;
    const int wid  = tid >> 5;
    const int lane = tid & 31;
    const int wm = wid >> 1;
    const int wn = wid & 1;

    const __half* Asrc = gHn_h + ((size_t)(p * B_ + b)) * LP * DH;
    const __half* Bhs  = gHn_h + ((size_t)((p + 1) * B_ + b)) * LP * DH;

    const uint32_t tA = sb, tBh = sb + CTILE2;

    for (int i = tid; i < 2 * 12 * 17; i += 256) {
        const int tile = i / 204;
        const int rem  = i % 204;
        const int r    = rem / 17;
        const int c    = rem % 17;
        *(uint4*)(csm + (size_t)tile * CTILE2 + (196 + r) * CRSB2 + c * 16) =
            make_uint4(0u, 0u, 0u, 0u);
    }
    for (int t = tid; t < LP * 16; t += 256) {
        const int row = t >> 4;
        const int ch  = t & 15;
        const uint32_t doff = (uint32_t)row * CRSB2 + ch * 16;
        const size_t   goff = (size_t)row * DH + ch * 8;
        cp16(tA  + doff, Asrc + goff);
        cp16(tBh + doff, Bhs + goff);
    }
    CP_COMMIT();
    if (tid < DH) {
        colsq[tid] = 0.f;
        s1s[tid] = gSh[(size_t)(p * B_ + b) * DH + tid];
        s2s[tid] = gSh[(size_t)((p + 1) * B_ + b) * DH + tid];
    }
    CP_WAIT0();
    __syncthreads();

    const uint32_t ar = (lane & 7) + ((lane >> 4) << 3);
    const uint32_t ac = ((lane >> 3) & 1) * 16;
    const uint32_t br = (lane & 7) + (((lane >> 3) & 1) << 3);
    const uint32_t bc = (uint32_t)(lane >> 4) * 16;

    uint32_t a_off[2], b_off[4];
#pragma unroll
    for (int mt = 0; mt < 2; mt++)
        a_off[mt] = ar * CRSB2 + (uint32_t)(wm * 32 + mt * 16) * 2 + ac;
#pragma unroll
    for (int g = 0; g < 4; g++)
        b_off[g] = br * CRSB2 + (uint32_t)(wn * 64 + g * 16) * 2 + bc;

    float acc[2][8][4];
#pragma unroll
    for (int mt = 0; mt < 2; mt++)
#pragma unroll
        for (int nt = 0; nt < 8; nt++)
#pragma unroll
            for (int e = 0; e < 4; e++) acc[mt][nt][e] = 0.f;

#pragma unroll
    for (int ks = 0; ks < 13; ks++) {
        const uint32_t kb = (uint32_t)ks * 16 * CRSB2;
        uint32_t ah[2][4];
#pragma unroll
        for (int mt = 0; mt < 2; mt++)
            ldx4t(ah[mt], tA + a_off[mt] + kb);
#pragma unroll
        for (int g = 0; g < 4; g++) {
            uint32_t bh[4];
            ldx4t(bh, tBh + b_off[g] + kb);
#pragma unroll
            for (int mt = 0; mt < 2; mt++) {
                mma16816(acc[mt][2 * g],     ah[mt], bh[0], bh[1]);
                mma16816(acc[mt][2 * g + 1], ah[mt], bh[2], bh[3]);
            }
        }
    }

    const float m1 = gM[p * B_ + b];
    const float m2 = gM[(p + 1) * B_ + b];
    const float c12 = (float)LP * m1 * m2;
    const int gid = lane >> 2;
    const int tig = lane & 3;
#pragma unroll
    for (int mt = 0; mt < 2; mt++) {
        const int d0 = wm * 32 + mt * 16 + gid;
        const float t1a = m2 * s1s[d0]     - c12;
        const float t1b = m2 * s1s[d0 + 8] - c12;
#pragma unroll
        for (int nt = 0; nt < 8; nt++) {
            const int e0 = wn * 64 + nt * 8 + 2 * tig;
            const float t2a = m1 * s2s[e0];
            const float t2b = m1 * s2s[e0 + 1];
            acc[mt][nt][0] -= t1a + t2a;
            acc[mt][nt][1] -= t1a + t2b;
            acc[mt][nt][2] -= t1b + t2a;
            acc[mt][nt][3] -= t1b + t2b;
        }
    }

#pragma unroll
    for (int nt = 0; nt < 8; nt++) {
        float s0 = acc[0][nt][0] * acc[0][nt][0] + acc[0][nt][2] * acc[0][nt][2]
                 + acc[1][nt][0] * acc[1][nt][0] + acc[1][nt][2] * acc[1][nt][2];
        float s1 = acc[0][nt][1] * acc[0][nt][1] + acc[0][nt][3] * acc[0][nt][3]
                 + acc[1][nt][1] * acc[1][nt][1] + acc[1][nt][3] * acc[1][nt][3];
#pragma unroll
        for (int o = 4; o <= 16; o <<= 1) {
            s0 += __shfl_xor_sync(0xffffffffu, s0, o);
            s1 += __shfl_xor_sync(0xffffffffu, s1, o);
        }
        if (lane < 4) {
            const int col = wn * 64 + nt * 8 + 2 * lane;
            atomicAdd(&colsq[col], s0);
            atomicAdd(&colsq[col + 1], s1);
        }
    }
    __syncthreads();

    float* outb = g_cov + ((size_t)(b * 3 + p)) * (DH * DH);
#pragma unroll
    for (int nt = 0; nt < 8; nt++) {
        const int col = wn * 64 + nt * 8 + 2 * tig;
        const float i0 = 1.0f / fmaxf(sqrtf(colsq[col]),     (float)LP * 1e-12f);
        const float i1 = 1.0f / fmaxf(sqrtf(colsq[col + 1]), (float)LP * 1e-12f);
#pragma unroll
        for (int mt = 0; mt < 2; mt++) {
            const int r0 = wm * 32 + mt * 16 + gid;
            float2 v0 = make_float2(acc[mt][nt][0] * i0, acc[mt][nt][1] * i1);
            float2 v1 = make_float2(acc[mt][nt][2] * i0, acc[mt][nt][3] * i1);
            *(float2*)(outb + (size_t)r0 * DH + col)       = v0;
            *(float2*)(outb + (size_t)(r0 + 8) * DH + col) = v1;
        }
    }
}

// =====================================================================
// K4: fused conv1 -> GELU -> conv2 ; emits flat as fp16 hi/lo (padded)
// =====================================================================
#define CONV_CS_B  (3 * 66 * 128 * 4)
#define CONV_SMEM  (CONV_CS_B + 3 * 3969 * 4)  // 149,004

__global__ void __launch_bounds__(256) k_conv(
    const float* __restrict__ w1, const float* __restrict__ w2)
{
    extern __shared__ char cvsm[];
    float* cs = (float*)cvsm;
    float* z1 = (float*)(cvsm + CONV_CS_B);
    __shared__ float w1s[81];
    __shared__ float w2s[81];

    const int b = blockIdx.x;
    const int tid = threadIdx.x;
    if (tid < 81) { w1s[tid] = w1[tid]; w2s[tid] = w2[tid]; }

    const float* cb = g_cov + (size_t)b * 3 * DH * DH;

#pragma unroll 1
    for (int ph = 0; ph < 2; ph++) {
        const int r0 = ph * 64;
        const int nr = ph ? 64 : 66;
        const int y0 = ph ? 32 : 0;
        const int ny = ph ? 31 : 32;
        __syncthreads();
        for (int i = tid; i < 3 * nr * 32; i += 256) {
            const int c  = i / (nr * 32);
            const int rr = (i / 32) % nr;
            const int q  = i % 32;
            *(float4*)(cs + (c * 66 + rr) * 128 + q * 4) =
                *(const float4*)(cb + (size_t)c * (DH * DH) + (r0 + rr) * DH + q * 4);
        }
        __syncthreads();
        for (int idx = tid; idx < 3 * ny * 63; idx += 256) {
            const int c = idx / (ny * 63);
            const int r = idx % (ny * 63);
            const int y = y0 + r / 63;
            const int x = r % 63;
            float s = 0.f;
#pragma unroll
            for (int ci = 0; ci < 3; ci++)
#pragma unroll
                for (int ky = 0; ky < 3; ky++)
#pragma unroll
                    for (int kx = 0; kx < 3; kx++)
                        s += cs[(ci * 66 + (2 * y + ky - r0)) * 128 + 2 * x + kx]
                           * w1s[((c * 3 + ci) * 3 + ky) * 3 + kx];
            s = 0.5f * s * (1.0f + erff(s * 0.70710678118654752f));
            z1[c * 3969 + y * 63 + x] = s;
        }
    }
    __syncthreads();

    __half* fh = gF_h + (size_t)b * FPAD;
    __half* fl = gF_l + (size_t)b * FPAD;
    for (int idx = tid; idx < FLATN; idx += 256) {
        const int c = idx / 961;
        const int r = idx % 961;
        const int y = r / 31, x = r % 31;
        float s = 0.f;
#pragma unroll
        for (int ci = 0; ci < 3; ci++)
#pragma unroll
            for (int ky = 0; ky < 3; ky++)
#pragma unroll
                for (int kx = 0; kx < 3; kx++)
                    s += z1[ci * 3969 + (2 * y + ky) * 63 + (2 * x + kx)]
                       * w2s[((c * 3 + ci) * 3 + ky) * 3 + kx];
        const __half hv = __float2half_rn(s);
        fh[idx] = hv;
        fl[idx] = __float2half_rn(s - __half2float(hv));
    }
    for (int idx = FLATN + tid; idx < FPAD; idx += 256) {
        fh[idx] = __float2half_rn(0.f);
        fl[idx] = __float2half_rn(0.f);
    }
}

// =====================================================================
// K5: classifier head via fp16 mma, 3-pass split, k-split=4 + atomicAdd
// =====================================================================
#define HRSB   80
#define HBRS   272
#define OFF_AH2 0
#define OFF_AL2 (64 * HRSB)
#define OFF_BH2 (2 * 64 * HRSB)
#define OFF_BL2 (OFF_BH2 + 32 * HBRS)
#define HSTAGE  (OFF_BL2 + 32 * HBRS)   // 27648
#define HEAD_SMEM (2 * HSTAGE)          // 55296

__device__ __forceinline__ void head_load_stage(
    uint32_t sb, int buf, int chunk, int m0, int n0, int tid)
{
    const uint32_t stg = sb + buf * HSTAGE;
    const bool in_cls = (chunk < HK_CLS_CHUNKS);
    const int  kr     = in_cls ? chunk * 32 : (chunk - HK_CLS_CHUNKS) * 32;
    const __half* Ah = in_cls ? gCls_h : gF_h;
    const __half* Al = in_cls ? gCls_l : gF_l;
    const __half* Bh = in_cls ? gW1_h  : gW2_h;
    const __half* Bl = in_cls ? gW1_l  : gW2_l;
    const int astr = in_cls ? D_ : FPAD;

    {
        const int idx = tid;
        const int row = idx >> 2;
        const int q   = idx & 3;
        const uint32_t doff = (uint32_t)row * HRSB + q * 16;
        const size_t goff = (size_t)(m0 + row) * astr + kr + q * 8;
        cp16(stg + OFF_AH2 + doff, Ah + goff);
        cp16(stg + OFF_AL2 + doff, Al + goff);
    }
#pragma unroll
    for (int j = 0; j < 2; j++) {
        const int idx = j * 256 + tid;
        const int row = idx >> 4;
        const int q   = idx & 15;
        const uint32_t doff = (uint32_t)row * HBRS + q * 16;
        const size_t goff = (size_t)(kr + row) * NPAD + n0 + q * 8;
        cp16(stg + OFF_BH2 + doff, Bh + goff);
        cp16(stg + OFF_BL2 + doff, Bl + goff);
    }
}

__global__ void __launch_bounds__(256) k_head_mma(float* __restrict__ out)
{
    extern __shared__ char hsm[];
    const uint32_t sb = smem_u32(hsm);
    const int tid  = threadIdx.x;
    const int wid  = tid >> 5;
    const int lane = tid & 31;
    const int wm = wid >> 2;
    const int wn = wid & 3;
    const int m0 = blockIdx.x * 64;
    const int n0 = blockIdx.y * 128;
    const int c0 = blockIdx.z * HK_SPLIT;

    const uint32_t a_row = (lane & 15);
    const uint32_t a_col = (uint32_t)(lane >> 4) * 16;
    const uint32_t br = (lane & 7) + (((lane >> 3) & 1) << 3);
    const uint32_t bc = (uint32_t)(lane >> 4) * 16;

    uint32_t a_off[2], b_off[2];
#pragma unroll
    for (int mt = 0; mt < 2; mt++)
        a_off[mt] = (uint32_t)(wm * 32 + mt * 16 + a_row) * HRSB + a_col;
#pragma unroll
    for (int g = 0; g < 2; g++)
        b_off[g] = br * HBRS + (uint32_t)(wn * 32 + g * 16) * 2 + bc;

    float acc[2][4][4];
#pragma unroll
    for (int mt = 0; mt < 2; mt++)
#pragma unroll
        for (int nf = 0; nf < 4; nf++)
#pragma unroll
            for (int e = 0; e < 4; e++) acc[mt][nf][e] = 0.f;

    head_load_stage(sb, 0, c0, m0, n0, tid);
    CP_COMMIT();

    for (int i = 0; i < HK_SPLIT; i++) {
        if (i + 1 < HK_SPLIT) {
            head_load_stage(sb, (i + 1) & 1, c0 + i + 1, m0, n0, tid);
            CP_COMMIT();
            CP_WAIT1();
        } else {
            CP_WAIT0();
        }
        __syncthreads();

        const uint32_t stg = sb + (i & 1) * HSTAGE;
#pragma unroll
        for (int ks = 0; ks < 2; ks++) {
            uint32_t ah[2][4], al[2][4];
#pragma unroll
            for (int mt = 0; mt < 2; mt++) {
                ldx4(ah[mt], stg + OFF_AH2 + a_off[mt] + ks * 32);
                ldx4(al[mt], stg + OFF_AL2 + a_off[mt] + ks * 32);
            }
            const uint32_t kbb = (uint32_t)ks * 16 * HBRS;
#pragma unroll
            for (int g = 0; g < 2; g++) {
                uint32_t bh[4], bl[4];
                ldx4t(bh, stg + OFF_BH2 + b_off[g] + kbb);
                ldx4t(bl, stg + OFF_BL2 + b_off[g] + kbb);
#pragma unroll
                for (int mt = 0; mt < 2; mt++) {
                    mma16816(acc[mt][2 * g],     ah[mt], bh[0], bh[1]);
                    mma16816(acc[mt][2 * g],     ah[mt], bl[0], bl[1]);
                    mma16816(acc[mt][2 * g],     al[mt], bh[0], bh[1]);
                    mma16816(acc[mt][2 * g + 1], ah[mt], bh[2], bh[3]);
                    mma16816(acc[mt][2 * g + 1], ah[mt], bl[2], bl[3]);
                    mma16816(acc[mt][2 * g + 1], al[mt], bh[2], bh[3]);
                }
            }
        }
        __syncthreads();
    }

    const int gid = lane >> 2;
    const int tig = lane & 3;
#pragma unroll
    for (int mt = 0; mt < 2; mt++) {
        const int r0 = m0 + wm * 32 + mt * 16 + gid;
#pragma unroll
        for (int nf = 0; nf < 4; nf++) {
            const int col = n0 + wn * 32 + nf * 8 + 2 * tig;
            if (col < NC) {
                atomicAdd(out + (size_t)r0 * NC + col,       0.5f * acc[mt][nf][0]);
                atomicAdd(out + (size_t)r0 * NC + col + 1,   0.5f * acc[mt][nf][1]);
                atomicAdd(out + (size_t)(r0 + 8) * NC + col,     0.5f * acc[mt][nf][2]);
                atomicAdd(out + (size_t)(r0 + 8) * NC + col + 1, 0.5f * acc[mt][nf][3]);
            }
        }
    }
}

// =====================================================================
// launch
// =====================================================================
extern "C" void kernel_launch(void* const* d_in, const int* in_sizes, int n_in,
                              void* d_out, int out_size)
{
    const float* cls_token = (const float*)d_in[0];
    const float* x         = (const float*)d_in[1];
    const float* proj_w    = (const float*)d_in[2];
    const float* proj_b    = (const float*)d_in[3];
    const float* ln_g      = (const float*)d_in[4];
    const float* ln_b      = (const float*)d_in[5];
    const float* conv1_w   = (const float*)d_in[6];
    const float* conv2_w   = (const float*)d_in[7];
    const float* cls1_w    = (const float*)d_in[8];
    const float* cls1_b    = (const float*)d_in[9];
    const float* cls2_w    = (const float*)d_in[10];
    const float* cls2_b    = (const float*)d_in[11];
    float* out = (float*)d_out;

    cudaFuncSetAttribute(k_gemm_mma,
                         cudaFuncAttributeMaxDynamicSharedMemorySize, GEMM_SMEM);
    cudaFuncSetAttribute(k_cov_mma,
                         cudaFuncAttributeMaxDynamicSharedMemorySize, COV_SMEM);
    cudaFuncSetAttribute(k_conv,
                         cudaFuncAttributeMaxDynamicSharedMemorySize, CONV_SMEM);
    cudaFuncSetAttribute(k_head_mma,
                         cudaFuncAttributeMaxDynamicSharedMemorySize, HEAD_SMEM);

    k_convA<<<2048, 256>>>(x);                                      // 0
    k_convW<<<dim3(HD / 32, D_ / 32), 256>>>(proj_w);               // 1
    k_convH<<<2048, 256>>>(cls1_w, cls2_w, cls_token,
                           cls1_b, cls2_b, out);                    // 2
    k_gemm_mma<<<dim3(392, 4), 128, GEMM_SMEM>>>(proj_b);           // 3 <- ncu probe
    k_lnc<<<NH * B_, 256>>>(ln_g, ln_b);                            // 4
    k_cov_mma<<<dim3(3, B_), 256, COV_SMEM>>>();                    // 5
    k_conv<<<B_, 256, CONV_SMEM>>>(conv1_w, conv2_w);               // 6
    k_head_mma<<<dim3(4, 8, 4), 256, HEAD_SMEM>>>(out);             // 7
}